// round 14
// baseline (speedup 1.0000x reference)
#include <cuda_runtime.h>
#include <math.h>

#define Nn 8192
#define Ee 131072
#define C0 64
#define C1 32
#define NSs 160     // 2*C0 + C1
#define NVv 128     // C0 + 2*C1
#define EPB 8       // edges per warp batch (edge kernel)
#define NPAIR 4     // EPB/2
#define EW 16       // warps per edge block (512 threads — proven config)

typedef unsigned long long ull;

// ---------------- static device scratch ----------------
__device__ float g_s[Nn * C0];
__device__ float g_v[Nn * C1 * 3];
__device__ float g_skip_s[Nn * C0];
__device__ float g_skip_v[Nn * C1 * 3];
__device__ float g_agg_s[Nn * NSs];
__device__ float g_agg_v[Nn * 3 * NVv];  // [n][ii][c]  (component-major)

__device__ __forceinline__ float silu_f(float x) {
    return __fdividef(x, 1.0f + __expf(-x));
}

// packed fp32x2 helpers (sm_100a): bit-exact dual fp32 FMA
__device__ __forceinline__ ull pack2(float x, float y) {
    ull r; asm("mov.b64 %0, {%1, %2};" : "=l"(r) : "f"(x), "f"(y)); return r;
}
__device__ __forceinline__ void unpack2(ull v, float& x, float& y) {
    asm("mov.b64 {%0, %1}, %2;" : "=f"(x), "=f"(y) : "l"(v));
}
__device__ __forceinline__ ull fma2(ull a, ull b, ull c) {
    ull d; asm("fma.rn.f32x2 %0, %1, %2, %3;" : "=l"(d) : "l"(a), "l"(b), "l"(c)); return d;
}
__device__ __forceinline__ ull dup2(float x) { return pack2(x, x); }
__device__ __forceinline__ ull lds64(const float* p) { return *(const ull*)p; }

// ---------------- kernel 1: node pre — node-paired fp32x2 (R13 proven) ----------------
#define PRE_SMEM_FLOATS (25600 + 8 * 320)

__global__ void __launch_bounds__(256) node_pre_kernel(
    const float* __restrict__ s_in, const float* __restrict__ v_in,
    const int* __restrict__ species,
    const float* __restrict__ Wskip0, const float* __restrict__ Wskip1,
    const float* __restrict__ Wu0, const float* __restrict__ Wu1)
{
    extern __shared__ float sm[];
    float* sWu0 = sm;                  // 4096
    float* sWu1 = sWu0 + 4096;         // 1024
    float* sWs0 = sWu1 + 1024;         // 16384
    float* sWs1 = sWs0 + 16384;        // 4096
    float* bufs = sWs1 + 4096;         // 8 warps * 320

    int tid = threadIdx.x;

    // zero aggregation buffers (kernel boundary orders this before edge_kernel)
    {
        int gt = blockIdx.x * 256 + tid;
        int gstride = gridDim.x * 256;
        float4 z4 = make_float4(0.f, 0.f, 0.f, 0.f);
        float4* az = (float4*)g_agg_s;
        for (int j = gt; j < Nn * NSs / 4; j += gstride) az[j] = z4;
        float4* bz = (float4*)g_agg_v;
        for (int j = gt; j < Nn * 3 * NVv / 4; j += gstride) bz[j] = z4;
    }

    for (int i = tid; i < 4096;  i += blockDim.x) sWu0[i] = Wu0[i];
    for (int i = tid; i < 1024;  i += blockDim.x) sWu1[i] = Wu1[i];
    for (int i = tid; i < 16384; i += blockDim.x) sWs0[i] = Wskip0[i];
    for (int i = tid; i < 4096;  i += blockDim.x) sWs1[i] = Wskip1[i];
    __syncthreads();

    int w = tid >> 5, lane = tid & 31;
    ull* sb2 = (ull*)(bufs + w * 320);      // 64 ull
    ull* vb2 = sb2 + 64;                    // 96 ull
    int warpsTotal = gridDim.x * 8;

    for (int p = blockIdx.x * 8 + w; p < Nn / 2; p += warpsTotal) {
        int n0 = 2 * p, n1 = n0 + 1;
        sb2[lane]      = pack2(s_in[n0 * 64 + lane],      s_in[n1 * 64 + lane]);
        sb2[lane + 32] = pack2(s_in[n0 * 64 + lane + 32], s_in[n1 * 64 + lane + 32]);
        vb2[lane]      = pack2(v_in[n0 * 96 + lane],      v_in[n1 * 96 + lane]);
        vb2[lane + 32] = pack2(v_in[n0 * 96 + lane + 32], v_in[n1 * 96 + lane + 32]);
        vb2[lane + 64] = pack2(v_in[n0 * 96 + lane + 64], v_in[n1 * 96 + lane + 64]);
        __syncwarp();
        int sp0 = species[n0];
        int sp1 = species[n1];
        const float* W0a = sWs0 + sp0 * 4096;
        const float* W0b = sWs0 + sp1 * 4096;
        const float* W1a = sWs1 + sp0 * 1024;
        const float* W1b = sWs1 + sp1 * 1024;

        ull aU0 = 0ull, aU1 = 0ull, aS0 = 0ull, aS1 = 0ull;
        #pragma unroll 8
        for (int c = 0; c < 64; c++) {
            ull xp = sb2[c];
            aU0 = fma2(xp, dup2(sWu0[c * 64 + lane]),      aU0);
            aU1 = fma2(xp, dup2(sWu0[c * 64 + lane + 32]), aU1);
            aS0 = fma2(xp, pack2(W0a[c * 64 + lane],      W0b[c * 64 + lane]),      aS0);
            aS1 = fma2(xp, pack2(W0a[c * 64 + lane + 32], W0b[c * 64 + lane + 32]), aS1);
        }
        {
            float lo, hi;
            unpack2(aU0, lo, hi);
            g_s[n0 * 64 + lane] = lo; g_s[n1 * 64 + lane] = hi;
            unpack2(aU1, lo, hi);
            g_s[n0 * 64 + lane + 32] = lo; g_s[n1 * 64 + lane + 32] = hi;
            unpack2(aS0, lo, hi);
            g_skip_s[n0 * 64 + lane] = lo; g_skip_s[n1 * 64 + lane] = hi;
            unpack2(aS1, lo, hi);
            g_skip_s[n0 * 64 + lane + 32] = lo; g_skip_s[n1 * 64 + lane + 32] = hi;
        }

        ull aV0 = 0ull, aV1 = 0ull, aV2 = 0ull, aK0 = 0ull, aK1 = 0ull, aK2 = 0ull;
        #pragma unroll 8
        for (int c = 0; c < 32; c++) {
            float wu = sWu1[c * 32 + lane];
            ull wup = dup2(wu);
            ull wkp = pack2(W1a[c * 32 + lane], W1b[c * 32 + lane]);
            ull x0 = vb2[c * 3], x1 = vb2[c * 3 + 1], x2 = vb2[c * 3 + 2];
            aV0 = fma2(x0, wup, aV0); aV1 = fma2(x1, wup, aV1); aV2 = fma2(x2, wup, aV2);
            aK0 = fma2(x0, wkp, aK0); aK1 = fma2(x1, wkp, aK1); aK2 = fma2(x2, wkp, aK2);
        }
        {
            float lo, hi;
            unpack2(aV0, lo, hi);
            g_v[n0 * 96 + lane * 3] = lo; g_v[n1 * 96 + lane * 3] = hi;
            unpack2(aV1, lo, hi);
            g_v[n0 * 96 + lane * 3 + 1] = lo; g_v[n1 * 96 + lane * 3 + 1] = hi;
            unpack2(aV2, lo, hi);
            g_v[n0 * 96 + lane * 3 + 2] = lo; g_v[n1 * 96 + lane * 3 + 2] = hi;
            unpack2(aK0, lo, hi);
            g_skip_v[n0 * 96 + lane * 3] = lo; g_skip_v[n1 * 96 + lane * 3] = hi;
            unpack2(aK1, lo, hi);
            g_skip_v[n0 * 96 + lane * 3 + 1] = lo; g_skip_v[n1 * 96 + lane * 3 + 1] = hi;
            unpack2(aK2, lo, hi);
            g_skip_v[n0 * 96 + lane * 3 + 2] = lo; g_skip_v[n1 * 96 + lane * 3 + 2] = hi;
        }
        __syncwarp();
    }
}

// ---------------- kernel 2: fused edge MLP + scatter — h2 in registers, shfl layer 3 ----------------
// per-warp smem: h1 [0:512), msg [512:1056)
__global__ void __launch_bounds__(32 * EW) edge_kernel(
    const float* __restrict__ radial, const float* __restrict__ Y0,
    const float* __restrict__ Y1,
    const int* __restrict__ senders, const int* __restrict__ receivers,
    const float* __restrict__ Wm1, const float* __restrict__ Wm2,
    const float* __restrict__ Wm3)
{
    extern __shared__ float sm[];
    float* sWm1 = sm;                 // 512
    float* sWm2 = sWm1 + 512;         // 4096
    float* sWm3 = sWm2 + 4096;        // 18432
    float* wb   = sWm3 + 18432;

    int tid = threadIdx.x, w = tid >> 5, lane = tid & 31;
    for (int i = tid; i < 512;   i += blockDim.x) sWm1[i] = Wm1[i];
    for (int i = tid; i < 4096;  i += blockDim.x) sWm2[i] = Wm2[i];
    for (int i = tid; i < 18432; i += blockDim.x) sWm3[i] = Wm3[i];
    __syncthreads();

    const int perW = 512 + 544;         // h1(pairs) + msg
    float* h1f = wb + w * perW;
    float* msg = h1f + 512;
    ull* h1u = (ull*)h1f;

    int nwarps = gridDim.x * EW;
    int gw = blockIdx.x * EW + w;
    const float inv_s3 = 0.57735026918962576f;

    for (int e0 = gw * EPB; e0 < Ee; e0 += nwarps * EPB) {
        // ---- layer 1 ----
        #pragma unroll
        for (int p = 0; p < NPAIR; p++) {
            float sv[2][2];
            #pragma unroll
            for (int hh = 0; hh < 2; hh++) {
                int e = e0 + 2 * p + hh;
                float rv = (lane < 8) ? radial[e * 8 + lane] : 0.f;
                float a0 = 0.f, a1 = 0.f;
                #pragma unroll
                for (int k = 0; k < 8; k++) {
                    float rk = __shfl_sync(0xffffffffu, rv, k);
                    a0 = fmaf(rk, sWm1[k * 64 + lane],      a0);
                    a1 = fmaf(rk, sWm1[k * 64 + lane + 32], a1);
                }
                sv[hh][0] = silu_f(a0);
                sv[hh][1] = silu_f(a1);
            }
            h1u[p * 64 + lane]      = pack2(sv[0][0], sv[1][0]);
            h1u[p * 64 + lane + 32] = pack2(sv[0][1], sv[1][1]);
        }
        __syncwarp();

        // ---- layer 2: h2 kept in registers (col lane -> h2a, col lane+32 -> h2b) ----
        ull h2a[NPAIR], h2b[NPAIR];
        {
            ull acc0[NPAIR], acc1[NPAIR];
            #pragma unroll
            for (int p = 0; p < NPAIR; p++) { acc0[p] = 0ull; acc1[p] = 0ull; }
            for (int k = 0; k < 64; k++) {
                float w0 = sWm2[k * 64 + lane];
                float w1 = sWm2[k * 64 + lane + 32];
                ull w0p = dup2(w0);
                ull w1p = dup2(w1);
                #pragma unroll
                for (int p = 0; p < NPAIR; p++) {
                    ull hp = h1u[p * 64 + k];
                    acc0[p] = fma2(hp, w0p, acc0[p]);
                    acc1[p] = fma2(hp, w1p, acc1[p]);
                }
            }
            #pragma unroll
            for (int p = 0; p < NPAIR; p++) {
                float x, y;
                unpack2(acc0[p], x, y);
                h2a[p] = pack2(silu_f(x), silu_f(y));
                unpack2(acc1[p], x, y);
                h2b[p] = pack2(silu_f(x), silu_f(y));
            }
        }

        // ---- layer 3: broadcast h2 column k via shfl (k<32 from h2a, k>=32 from h2b) ----
        ull m2[NPAIR * 9];
        #pragma unroll
        for (int i = 0; i < NPAIR * 9; i++) m2[i] = 0ull;

        for (int k = 0; k < 32; k++) {
            ull hp[NPAIR];
            #pragma unroll
            for (int p = 0; p < NPAIR; p++)
                hp[p] = __shfl_sync(0xffffffffu, h2a[p], k);
            #pragma unroll
            for (int r = 0; r < 9; r++) {
                float wv = sWm3[k * 288 + lane + 32 * r];
                ull wp = dup2(wv);
                #pragma unroll
                for (int p = 0; p < NPAIR; p++)
                    m2[p * 9 + r] = fma2(hp[p], wp, m2[p * 9 + r]);
            }
        }
        for (int k = 32; k < 64; k++) {
            ull hp[NPAIR];
            #pragma unroll
            for (int p = 0; p < NPAIR; p++)
                hp[p] = __shfl_sync(0xffffffffu, h2b[p], k - 32);
            #pragma unroll
            for (int r = 0; r < 9; r++) {
                float wv = sWm3[k * 288 + lane + 32 * r];
                ull wp = dup2(wv);
                #pragma unroll
                for (int p = 0; p < NPAIR; p++)
                    m2[p * 9 + r] = fma2(hp[p], wp, m2[p * 9 + r]);
            }
        }

        // ---- messages + scatter ----
        #pragma unroll
        for (int t = 0; t < EPB; t++) {
            int pp = t >> 1, hh = t & 1;
            float mr[9];
            #pragma unroll
            for (int r = 0; r < 9; r++) {
                float lo, hi;
                unpack2(m2[pp * 9 + r], lo, hi);
                mr[r] = hh ? hi : lo;
            }
            int e = e0 + t;
            int snd = senders[e];
            int rcv = receivers[e];
            float m0  = g_s[snd * 64 + lane];
            float m1  = g_s[snd * 64 + lane + 32];
            float mv0 = g_v[snd * 96 + lane * 3];
            float mv1 = g_v[snd * 96 + lane * 3 + 1];
            float mv2 = g_v[snd * 96 + lane * 3 + 2];
            float y0  = Y0[e];
            float y10 = Y1[e * 3], y11 = Y1[e * 3 + 1], y12 = Y1[e * 3 + 2];
            float dot = (mv0 * y10 + mv1 * y11 + mv2 * y12) * inv_s3;

            msg[lane]       = m0 * mr[0];
            msg[32 + lane]  = m1 * mr[1];
            msg[64 + lane]  = m0 * y0 * mr[2];
            msg[96 + lane]  = m1 * y0 * mr[3];
            msg[128 + lane] = dot * mr[4];
            float vv5 = mr[5];
            msg[160 + lane]       = mv0 * vv5;
            msg[160 + 128 + lane] = mv1 * vv5;
            msg[160 + 256 + lane] = mv2 * vv5;
            float f6 = m0 * mr[6];
            msg[160 + 32 + lane]        = f6 * y10;
            msg[160 + 128 + 32 + lane]  = f6 * y11;
            msg[160 + 256 + 32 + lane]  = f6 * y12;
            float f7 = m1 * mr[7];
            msg[160 + 64 + lane]        = f7 * y10;
            msg[160 + 128 + 64 + lane]  = f7 * y11;
            msg[160 + 256 + 64 + lane]  = f7 * y12;
            float f8 = y0 * mr[8];
            msg[160 + 96 + lane]        = mv0 * f8;
            msg[160 + 128 + 96 + lane]  = mv1 * f8;
            msg[160 + 256 + 96 + lane]  = mv2 * f8;
            __syncwarp();

            float* aggs = g_agg_s + (long)rcv * NSs;
            float* aggv = g_agg_v + (long)rcv * (NVv * 3);
            const float4* m4 = (const float4*)msg;
            #pragma unroll
            for (int gi = 0; gi < 5; gi++) {
                int g = lane + gi * 32;
                if (g < 136) {
                    float4 vv = m4[g];
                    float* p = (g < 40) ? (aggs + 4 * g) : (aggv + 4 * (g - 40));
                    asm volatile("red.global.add.v4.f32 [%0], {%1, %2, %3, %4};"
                                 :: "l"(p), "f"(vv.x), "f"(vv.y), "f"(vv.z), "f"(vv.w)
                                 : "memory");
                }
            }
            __syncwarp();
        }
    }
}

// ---------------- node_kernel: full node path in one launch (proven R9 version) ----------------
// smem (floats): region0 [0, 21504) multi-use; s1s/v1s [21504, 26112); sq [26112, 26688)
#define S1OFF  21504
#define SQOFF  26112
#define NODE_SMEM_FLOATS 26688

__device__ void quantum_rows(const float* sOut, const float* sq, int row0,
                             int nrows, float* out0)
{
    int t = threadIdx.x;
    const float* sWq = sq;
    const float* cw  = sq + 512;
    const float* sw_ = sq + 536;
    const float* sWo = sq + 560;
    float bo0 = sq[568];
    int w = t >> 5, lane = t & 31;

    #pragma unroll 1
    for (int pass = 0; pass < nrows / 8; pass++) {
        int r = pass * 8 + w;
        int n = row0 + r;
        const float* srow = sOut + r * 65;
        float s_lo = srow[lane];
        float s_hi = srow[lane + 32];

        float frow[8];
        #pragma unroll
        for (int q = 0; q < 8; q++)
            frow[q] = s_lo * sWq[lane * 8 + q] + s_hi * sWq[(lane + 32) * 8 + q];
        #pragma unroll
        for (int q = 0; q < 8; q++) {
            #pragma unroll
            for (int off = 16; off > 0; off >>= 1)
                frow[q] += __shfl_xor_sync(0xffffffffu, frow[q], off);
        }

        float cs[8], sn[8];
        #pragma unroll
        for (int q = 0; q < 8; q++) {
            float a = 0.5f * frow[q];
            __sincosf(a, &sn[q], &cs[q]);
        }
        float lf = 1.f;
        #pragma unroll
        for (int j = 0; j < 5; j++) {
            int q = 4 - j;
            lf *= ((lane >> j) & 1) ? sn[q] : cs[q];
        }
        float amp[8];
        #pragma unroll
        for (int l = 0; l < 8; l++) {
            float f = lf;
            f *= (l & 4) ? sn[5] : cs[5];
            f *= (l & 2) ? sn[6] : cs[6];
            f *= (l & 1) ? sn[7] : cs[7];
            amp[l] = f;
        }

        #pragma unroll
        for (int L = 0; L < 3; L++) {
            #pragma unroll
            for (int q = 0; q < 8; q++) {
                float c = cw[L * 8 + q], s = sw_[L * 8 + q];
                const int b = 7 - q;
                if (b >= 3) {
                    const int m = 1 << (b - 3);
                    int bit = (lane >> (b - 3)) & 1;
                    #pragma unroll
                    for (int l = 0; l < 8; l++) {
                        float p = __shfl_xor_sync(0xffffffffu, amp[l], m);
                        amp[l] = bit ? fmaf(s, p, c * amp[l]) : (c * amp[l] - s * p);
                    }
                } else {
                    const int tm = 1 << b;
                    #pragma unroll
                    for (int l = 0; l < 8; l++) {
                        if (!(l & tm)) {
                            float a0 = amp[l], a1 = amp[l | tm];
                            amp[l]      = c * a0 - s * a1;
                            amp[l | tm] = fmaf(s, a0, c * a1);
                        }
                    }
                }
            }
            #pragma unroll
            for (int q = 0; q < 8; q++) {
                const int bc = 7 - q;
                const int bt = 7 - ((q + 1) & 7);
                if (bt >= 3) {
                    const int m = 1 << (bt - 3);
                    #pragma unroll
                    for (int l = 0; l < 8; l++) {
                        float p = __shfl_xor_sync(0xffffffffu, amp[l], m);
                        int ctrl = (bc >= 3) ? ((lane >> (bc - 3)) & 1) : ((l >> bc) & 1);
                        amp[l] = ctrl ? p : amp[l];
                    }
                } else {
                    const int tm = 1 << bt;
                    if (bc >= 3) {
                        int ctrl = (lane >> (bc - 3)) & 1;
                        #pragma unroll
                        for (int l = 0; l < 8; l++) {
                            if (!(l & tm)) {
                                float a = amp[l], bb = amp[l | tm];
                                amp[l]      = ctrl ? bb : a;
                                amp[l | tm] = ctrl ? a : bb;
                            }
                        }
                    } else {
                        #pragma unroll
                        for (int l = 0; l < 8; l++) {
                            if (!(l & tm) && ((l >> bc) & 1)) {
                                float tmp = amp[l];
                                amp[l] = amp[l | tm];
                                amp[l | tm] = tmp;
                            }
                        }
                    }
                }
            }
        }

        float tsum = 0.f, tb0 = 0.f, tb1 = 0.f, tb2 = 0.f;
        #pragma unroll
        for (int l = 0; l < 8; l++) {
            float p = amp[l] * amp[l];
            tsum += p;
            tb0 += (l & 1) ? -p : p;
            tb1 += (l & 2) ? -p : p;
            tb2 += (l & 4) ? -p : p;
        }
        float lanesum = 0.f;
        #pragma unroll
        for (int q = 0; q < 5; q++) {
            float sgn = ((lane >> (4 - q)) & 1) ? -1.f : 1.f;
            lanesum = fmaf(sgn * sWo[q], 1.f, lanesum);
        }
        float op = sWo[7] * tb0 + sWo[6] * tb1 + sWo[5] * tb2 + tsum * lanesum;
        #pragma unroll
        for (int o = 16; o > 0; o >>= 1)
            op += __shfl_xor_sync(0xffffffffu, op, o);
        if (lane == 0) out0[n] = op + bo0;
    }
}

__global__ void __launch_bounds__(256, 2) node_kernel(
    const float* __restrict__ Wd0, const float* __restrict__ Wd1,
    const float* __restrict__ Wt0, const float* __restrict__ Wt1,
    const float* __restrict__ x_node,
    const float* __restrict__ Wq, const float* __restrict__ wqml,
    const float* __restrict__ Wo, const float* __restrict__ bo,
    float* __restrict__ out0, float* __restrict__ outS, float* __restrict__ outV)
{
    extern __shared__ float smg[];
    float* sq = smg + SQOFF;
    int t = threadIdx.x;
    const float inv16 = 1.0f / 16.0f;

    for (int i = t; i < 512; i += 256) sq[i] = Wq[i];
    if (t < 24) {
        float ang = 0.5f * wqml[t];
        sq[512 + t] = cosf(ang);
        sq[536 + t] = sinf(ang);
    }
    if (t < 8)  sq[560 + t] = Wo[t];
    if (t == 0) sq[568] = bo[0];

    if (blockIdx.x < 128) {
        // =================== s branch: 64 nodes ===================
        int row0 = blockIdx.x * 64;
        float* sA1 = smg;              // 64 x 164
        float* sB1 = smg + 10496;      // 160 x 68
        float* s1s = smg + S1OFF;      // 64 x 68

        for (int i4 = t; i4 < 64 * 40; i4 += 256) {
            int r = i4 / 40, c4 = i4 - r * 40;
            *(float4*)(sA1 + r * 164 + c4 * 4) =
                *(const float4*)(g_agg_s + (long)(row0 + r) * 160 + c4 * 4);
        }
        for (int i4 = t; i4 < 160 * 16; i4 += 256) {
            int r = i4 >> 4, c4 = i4 & 15;
            *(float4*)(sB1 + r * 68 + c4 * 4) = *(const float4*)(Wd0 + r * 64 + c4 * 4);
        }
        __syncthreads();

        int tx = t & 15, ty = t >> 4;   // TX=16, TY=16, TM=4
        {
            ull acc[4][2];
            #pragma unroll
            for (int mi = 0; mi < 4; mi++) { acc[mi][0] = 0ull; acc[mi][1] = 0ull; }
            const float* aB = sA1 + ty * 4 * 164;
            const float* bB = sB1 + 4 * tx;
            #pragma unroll 4
            for (int k = 0; k < 160; k++) {
                ull b0 = lds64(bB + k * 68);
                ull b1 = lds64(bB + k * 68 + 2);
                #pragma unroll
                for (int mi = 0; mi < 4; mi++) {
                    ull ad = dup2(aB[mi * 164 + k]);
                    acc[mi][0] = fma2(b0, ad, acc[mi][0]);
                    acc[mi][1] = fma2(b1, ad, acc[mi][1]);
                }
            }
            #pragma unroll
            for (int mi = 0; mi < 4; mi++) {
                float v0, v1, v2, v3;
                unpack2(acc[mi][0], v0, v1);
                unpack2(acc[mi][1], v2, v3);
                *(float4*)(s1s + (ty * 4 + mi) * 68 + 4 * tx) =
                    make_float4(v0 * inv16, v1 * inv16, v2 * inv16, v3 * inv16);
            }
        }
        __syncthreads();

        // phase 2: outS = (x (x) s1) @ Wt0 + skip; expansion fused into mainloop
        float* sB2 = smg;              // 256 x 68
        for (int i4 = t; i4 < 256 * 16; i4 += 256) {
            int r = i4 >> 4, c4 = i4 & 15;
            *(float4*)(sB2 + r * 68 + c4 * 4) = *(const float4*)(Wt0 + r * 64 + c4 * 4);
        }
        float xr[4][4];
        #pragma unroll
        for (int mi = 0; mi < 4; mi++) {
            float4 xq = *(const float4*)(x_node + (row0 + ty * 4 + mi) * 4);
            xr[mi][0] = xq.x; xr[mi][1] = xq.y; xr[mi][2] = xq.z; xr[mi][3] = xq.w;
        }
        __syncthreads();

        float ov[4][4];
        {
            ull acc[4][2];
            #pragma unroll
            for (int mi = 0; mi < 4; mi++) { acc[mi][0] = 0ull; acc[mi][1] = 0ull; }
            const float* bB = sB2 + 4 * tx;
            const float* s1B = s1s + ty * 4 * 68;
            #pragma unroll 1
            for (int a = 0; a < 4; a++) {
                const float* bA = bB + a * 64 * 68;
                #pragma unroll 4
                for (int c = 0; c < 64; c++) {
                    ull b0 = lds64(bA + c * 68);
                    ull b1 = lds64(bA + c * 68 + 2);
                    #pragma unroll
                    for (int mi = 0; mi < 4; mi++) {
                        float sv = s1B[mi * 68 + c];
                        ull ad = dup2(xr[mi][a] * sv);
                        acc[mi][0] = fma2(b0, ad, acc[mi][0]);
                        acc[mi][1] = fma2(b1, ad, acc[mi][1]);
                    }
                }
            }
            #pragma unroll
            for (int mi = 0; mi < 4; mi++) {
                int row = row0 + ty * 4 + mi;
                float v0, v1, v2, v3;
                unpack2(acc[mi][0], v0, v1);
                unpack2(acc[mi][1], v2, v3);
                float4 sk = *(const float4*)(g_skip_s + (long)row * 64 + 4 * tx);
                ov[mi][0] = v0 + sk.x; ov[mi][1] = v1 + sk.y;
                ov[mi][2] = v2 + sk.z; ov[mi][3] = v3 + sk.w;
            }
        }
        __syncthreads();                 // sB2 dead
        float* sOut = smg;               // 64 x 65
        #pragma unroll
        for (int mi = 0; mi < 4; mi++) {
            int r = ty * 4 + mi;
            int row = row0 + r;
            *(float4*)(outS + (long)row * 64 + 4 * tx) =
                make_float4(ov[mi][0], ov[mi][1], ov[mi][2], ov[mi][3]);
            sOut[r * 65 + 4 * tx]     = ov[mi][0];
            sOut[r * 65 + 4 * tx + 1] = ov[mi][1];
            sOut[r * 65 + 4 * tx + 2] = ov[mi][2];
            sOut[r * 65 + 4 * tx + 3] = ov[mi][3];
        }
        __syncthreads();

        quantum_rows(sOut, sq, row0, 64, out0);
    } else {
        // =================== v branch: 128 rows of (3n+ii) ===================
        int row0 = (blockIdx.x - 128) * 128;
        float* sA  = smg;              // 128 x 132
        float* sB1 = smg + 16896;      // 128 x 36
        float* v1s = smg + S1OFF;      // 128 x 36

        for (int i4 = t; i4 < 128 * 32; i4 += 256) {
            int r = i4 >> 5, c4 = i4 & 31;
            *(float4*)(sA + r * 132 + c4 * 4) =
                *(const float4*)(g_agg_v + (long)(row0 + r) * 128 + c4 * 4);
        }
        for (int i4 = t; i4 < 128 * 8; i4 += 256) {
            int r = i4 >> 3, c4 = i4 & 7;
            *(float4*)(sB1 + r * 36 + c4 * 4) = *(const float4*)(Wd1 + r * 32 + c4 * 4);
        }
        __syncthreads();

        int tx = t & 7, ty = t >> 3;    // TX=8, TY=32, TM=4
        {
            ull acc[4][2];
            #pragma unroll
            for (int mi = 0; mi < 4; mi++) { acc[mi][0] = 0ull; acc[mi][1] = 0ull; }
            const float* aB = sA + ty * 4 * 132;
            const float* bB = sB1 + 4 * tx;
            #pragma unroll 4
            for (int k = 0; k < 128; k++) {
                ull b0 = lds64(bB + k * 36);
                ull b1 = lds64(bB + k * 36 + 2);
                #pragma unroll
                for (int mi = 0; mi < 4; mi++) {
                    ull ad = dup2(aB[mi * 132 + k]);
                    acc[mi][0] = fma2(b0, ad, acc[mi][0]);
                    acc[mi][1] = fma2(b1, ad, acc[mi][1]);
                }
            }
            #pragma unroll
            for (int mi = 0; mi < 4; mi++) {
                float v0, v1, v2, v3;
                unpack2(acc[mi][0], v0, v1);
                unpack2(acc[mi][1], v2, v3);
                *(float4*)(v1s + (ty * 4 + mi) * 36 + 4 * tx) =
                    make_float4(v0 * inv16, v1 * inv16, v2 * inv16, v3 * inv16);
            }
        }
        __syncthreads();

        float* sB2 = smg;              // 128 x 36
        for (int i4 = t; i4 < 128 * 8; i4 += 256) {
            int r = i4 >> 3, c4 = i4 & 7;
            *(float4*)(sB2 + r * 36 + c4 * 4) = *(const float4*)(Wt1 + r * 32 + c4 * 4);
        }
        float xr[4][4];
        #pragma unroll
        for (int mi = 0; mi < 4; mi++) {
            int rr = row0 + ty * 4 + mi;
            float4 xq = *(const float4*)(x_node + (rr / 3) * 4);
            xr[mi][0] = xq.x; xr[mi][1] = xq.y; xr[mi][2] = xq.z; xr[mi][3] = xq.w;
        }
        __syncthreads();

        {
            ull acc[4][2];
            #pragma unroll
            for (int mi = 0; mi < 4; mi++) { acc[mi][0] = 0ull; acc[mi][1] = 0ull; }
            const float* bB = sB2 + 4 * tx;
            const float* v1B = v1s + ty * 4 * 36;
            #pragma unroll 1
            for (int a = 0; a < 4; a++) {
                const float* bA = bB + a * 32 * 36;
                #pragma unroll 4
                for (int c = 0; c < 32; c++) {
                    ull b0 = lds64(bA + c * 36);
                    ull b1 = lds64(bA + c * 36 + 2);
                    #pragma unroll
                    for (int mi = 0; mi < 4; mi++) {
                        float sv = v1B[mi * 36 + c];
                        ull ad = dup2(xr[mi][a] * sv);
                        acc[mi][0] = fma2(b0, ad, acc[mi][0]);
                        acc[mi][1] = fma2(b1, ad, acc[mi][1]);
                    }
                }
            }
            #pragma unroll
            for (int mi = 0; mi < 4; mi++) {
                int row = row0 + ty * 4 + mi;
                float vv[4];
                unpack2(acc[mi][0], vv[0], vv[1]);
                unpack2(acc[mi][1], vv[2], vv[3]);
                int n = row / 3, ii = row - 3 * n;
                #pragma unroll
                for (int j = 0; j < 4; j++) {
                    int c = 4 * tx + j;
                    outV[(long)n * 96 + c * 3 + ii] =
                        vv[j] + g_skip_v[(long)n * 96 + c * 3 + ii];
                }
            }
        }
    }
}

// ---------------- launch ----------------
extern "C" void kernel_launch(void* const* d_in, const int* in_sizes, int n_in,
                              void* d_out, int out_size) {
    const float* s_in     = (const float*)d_in[0];
    const float* v_in     = (const float*)d_in[1];
    const float* x_node   = (const float*)d_in[2];
    const float* radial   = (const float*)d_in[3];
    const float* Y0       = (const float*)d_in[4];
    const float* Y1       = (const float*)d_in[5];
    const int*   species  = (const int*)d_in[6];
    const int*   senders  = (const int*)d_in[7];
    const int*   receivers= (const int*)d_in[8];
    const float* Wskip0   = (const float*)d_in[9];
    const float* Wskip1   = (const float*)d_in[10];
    const float* Wu0      = (const float*)d_in[11];
    const float* Wu1      = (const float*)d_in[12];
    const float* Wm1      = (const float*)d_in[13];
    const float* Wm2      = (const float*)d_in[14];
    const float* Wm3      = (const float*)d_in[15];
    const float* Wd0      = (const float*)d_in[16];
    const float* Wd1      = (const float*)d_in[17];
    const float* Wt0      = (const float*)d_in[18];
    const float* Wt1      = (const float*)d_in[19];
    const float* Wq       = (const float*)d_in[20];
    const float* wqml     = (const float*)d_in[21];
    const float* Wo       = (const float*)d_in[22];
    const float* bo       = (const float*)d_in[23];

    float* out0 = (float*)d_out;
    float* outS = out0 + Nn;
    float* outV = outS + Nn * C0;

    static bool attr_done = false;
    size_t smem_pre  = PRE_SMEM_FLOATS * sizeof(float);                    // ~112.6 KB
    size_t smem_edge = (512 + 4096 + 18432 + EW * 1056) * sizeof(float);   // ~158 KB
    size_t smem_node = NODE_SMEM_FLOATS * sizeof(float);   // ~106.8 KB -> 2 blocks/SM
    if (!attr_done) {
        cudaFuncSetAttribute(node_pre_kernel, cudaFuncAttributeMaxDynamicSharedMemorySize, (int)smem_pre);
        cudaFuncSetAttribute(edge_kernel,     cudaFuncAttributeMaxDynamicSharedMemorySize, (int)smem_edge);
        cudaFuncSetAttribute(node_kernel,     cudaFuncAttributeMaxDynamicSharedMemorySize, (int)smem_node);
        attr_done = true;
    }

    node_pre_kernel<<<296, 256, smem_pre>>>(s_in, v_in, species, Wskip0, Wskip1, Wu0, Wu1);
    edge_kernel<<<148, 32 * EW, smem_edge>>>(radial, Y0, Y1, senders, receivers, Wm1, Wm2, Wm3);
    node_kernel<<<320, 256, smem_node>>>(Wd0, Wd1, Wt0, Wt1, x_node, Wq, wqml, Wo, bo,
                                         out0, outS, outV);
}

// round 15
// speedup vs baseline: 1.0372x; 1.0372x over previous
#include <cuda_runtime.h>
#include <math.h>

#define Nn 8192
#define Ee 131072
#define C0 64
#define C1 32
#define NSs 160     // 2*C0 + C1
#define NVv 128     // C0 + 2*C1
#define EPB 8       // edges per warp batch (edge kernel)
#define NPAIR 4     // EPB/2
#define EW 16       // warps per edge block (512 threads — proven config)

typedef unsigned long long ull;

// ---------------- static device scratch ----------------
__device__ float g_s[Nn * C0];
__device__ float g_v[Nn * C1 * 3];
__device__ float g_skip_s[Nn * C0];
__device__ float g_skip_v[Nn * C1 * 3];
__device__ float g_agg_s[Nn * NSs];
__device__ float g_agg_v[Nn * 3 * NVv];  // [n][ii][c]  (component-major)

__device__ __forceinline__ float silu_f(float x) {
    return __fdividef(x, 1.0f + __expf(-x));
}

// packed fp32x2 helpers (sm_100a): bit-exact dual fp32 FMA
__device__ __forceinline__ ull pack2(float x, float y) {
    ull r; asm("mov.b64 %0, {%1, %2};" : "=l"(r) : "f"(x), "f"(y)); return r;
}
__device__ __forceinline__ void unpack2(ull v, float& x, float& y) {
    asm("mov.b64 {%0, %1}, %2;" : "=f"(x), "=f"(y) : "l"(v));
}
__device__ __forceinline__ ull fma2(ull a, ull b, ull c) {
    ull d; asm("fma.rn.f32x2 %0, %1, %2, %3;" : "=l"(d) : "l"(a), "l"(b), "l"(c)); return d;
}
__device__ __forceinline__ ull dup2(float x) { return pack2(x, x); }
__device__ __forceinline__ ull lds64(const float* p) { return *(const ull*)p; }

// ---------------- kernel 1: node pre — node-paired fp32x2 (R13 proven) ----------------
#define PRE_SMEM_FLOATS (25600 + 8 * 320)

__global__ void __launch_bounds__(256) node_pre_kernel(
    const float* __restrict__ s_in, const float* __restrict__ v_in,
    const int* __restrict__ species,
    const float* __restrict__ Wskip0, const float* __restrict__ Wskip1,
    const float* __restrict__ Wu0, const float* __restrict__ Wu1)
{
    extern __shared__ float sm[];
    float* sWu0 = sm;                  // 4096
    float* sWu1 = sWu0 + 4096;         // 1024
    float* sWs0 = sWu1 + 1024;         // 16384
    float* sWs1 = sWs0 + 16384;        // 4096
    float* bufs = sWs1 + 4096;         // 8 warps * 320

    int tid = threadIdx.x;

    // zero aggregation buffers (kernel boundary orders this before edge_kernel)
    {
        int gt = blockIdx.x * 256 + tid;
        int gstride = gridDim.x * 256;
        float4 z4 = make_float4(0.f, 0.f, 0.f, 0.f);
        float4* az = (float4*)g_agg_s;
        for (int j = gt; j < Nn * NSs / 4; j += gstride) az[j] = z4;
        float4* bz = (float4*)g_agg_v;
        for (int j = gt; j < Nn * 3 * NVv / 4; j += gstride) bz[j] = z4;
    }

    for (int i = tid; i < 4096;  i += blockDim.x) sWu0[i] = Wu0[i];
    for (int i = tid; i < 1024;  i += blockDim.x) sWu1[i] = Wu1[i];
    for (int i = tid; i < 16384; i += blockDim.x) sWs0[i] = Wskip0[i];
    for (int i = tid; i < 4096;  i += blockDim.x) sWs1[i] = Wskip1[i];
    __syncthreads();

    int w = tid >> 5, lane = tid & 31;
    ull* sb2 = (ull*)(bufs + w * 320);      // 64 ull
    ull* vb2 = sb2 + 64;                    // 96 ull
    int warpsTotal = gridDim.x * 8;

    for (int p = blockIdx.x * 8 + w; p < Nn / 2; p += warpsTotal) {
        int n0 = 2 * p, n1 = n0 + 1;
        sb2[lane]      = pack2(s_in[n0 * 64 + lane],      s_in[n1 * 64 + lane]);
        sb2[lane + 32] = pack2(s_in[n0 * 64 + lane + 32], s_in[n1 * 64 + lane + 32]);
        vb2[lane]      = pack2(v_in[n0 * 96 + lane],      v_in[n1 * 96 + lane]);
        vb2[lane + 32] = pack2(v_in[n0 * 96 + lane + 32], v_in[n1 * 96 + lane + 32]);
        vb2[lane + 64] = pack2(v_in[n0 * 96 + lane + 64], v_in[n1 * 96 + lane + 64]);
        __syncwarp();
        int sp0 = species[n0];
        int sp1 = species[n1];
        const float* W0a = sWs0 + sp0 * 4096;
        const float* W0b = sWs0 + sp1 * 4096;
        const float* W1a = sWs1 + sp0 * 1024;
        const float* W1b = sWs1 + sp1 * 1024;

        ull aU0 = 0ull, aU1 = 0ull, aS0 = 0ull, aS1 = 0ull;
        #pragma unroll 8
        for (int c = 0; c < 64; c++) {
            ull xp = sb2[c];
            aU0 = fma2(xp, dup2(sWu0[c * 64 + lane]),      aU0);
            aU1 = fma2(xp, dup2(sWu0[c * 64 + lane + 32]), aU1);
            aS0 = fma2(xp, pack2(W0a[c * 64 + lane],      W0b[c * 64 + lane]),      aS0);
            aS1 = fma2(xp, pack2(W0a[c * 64 + lane + 32], W0b[c * 64 + lane + 32]), aS1);
        }
        {
            float lo, hi;
            unpack2(aU0, lo, hi);
            g_s[n0 * 64 + lane] = lo; g_s[n1 * 64 + lane] = hi;
            unpack2(aU1, lo, hi);
            g_s[n0 * 64 + lane + 32] = lo; g_s[n1 * 64 + lane + 32] = hi;
            unpack2(aS0, lo, hi);
            g_skip_s[n0 * 64 + lane] = lo; g_skip_s[n1 * 64 + lane] = hi;
            unpack2(aS1, lo, hi);
            g_skip_s[n0 * 64 + lane + 32] = lo; g_skip_s[n1 * 64 + lane + 32] = hi;
        }

        ull aV0 = 0ull, aV1 = 0ull, aV2 = 0ull, aK0 = 0ull, aK1 = 0ull, aK2 = 0ull;
        #pragma unroll 8
        for (int c = 0; c < 32; c++) {
            float wu = sWu1[c * 32 + lane];
            ull wup = dup2(wu);
            ull wkp = pack2(W1a[c * 32 + lane], W1b[c * 32 + lane]);
            ull x0 = vb2[c * 3], x1 = vb2[c * 3 + 1], x2 = vb2[c * 3 + 2];
            aV0 = fma2(x0, wup, aV0); aV1 = fma2(x1, wup, aV1); aV2 = fma2(x2, wup, aV2);
            aK0 = fma2(x0, wkp, aK0); aK1 = fma2(x1, wkp, aK1); aK2 = fma2(x2, wkp, aK2);
        }
        {
            float lo, hi;
            unpack2(aV0, lo, hi);
            g_v[n0 * 96 + lane * 3] = lo; g_v[n1 * 96 + lane * 3] = hi;
            unpack2(aV1, lo, hi);
            g_v[n0 * 96 + lane * 3 + 1] = lo; g_v[n1 * 96 + lane * 3 + 1] = hi;
            unpack2(aV2, lo, hi);
            g_v[n0 * 96 + lane * 3 + 2] = lo; g_v[n1 * 96 + lane * 3 + 2] = hi;
            unpack2(aK0, lo, hi);
            g_skip_v[n0 * 96 + lane * 3] = lo; g_skip_v[n1 * 96 + lane * 3] = hi;
            unpack2(aK1, lo, hi);
            g_skip_v[n0 * 96 + lane * 3 + 1] = lo; g_skip_v[n1 * 96 + lane * 3 + 1] = hi;
            unpack2(aK2, lo, hi);
            g_skip_v[n0 * 96 + lane * 3 + 2] = lo; g_skip_v[n1 * 96 + lane * 3 + 2] = hi;
        }
        __syncwarp();
    }
}

// ---------------- kernel 2: fused edge MLP (fp32x2) + scatter — R13 body, double-buffered msg ----------------
// per-warp smem: h1 [0:512), h2 [512:1024), msg double buffer [1024:2112)
__global__ void __launch_bounds__(32 * EW) edge_kernel(
    const float* __restrict__ radial, const float* __restrict__ Y0,
    const float* __restrict__ Y1,
    const int* __restrict__ senders, const int* __restrict__ receivers,
    const float* __restrict__ Wm1, const float* __restrict__ Wm2,
    const float* __restrict__ Wm3)
{
    extern __shared__ float sm[];
    float* sWm1 = sm;                 // 512
    float* sWm2 = sWm1 + 512;         // 4096
    float* sWm3 = sWm2 + 4096;        // 18432
    float* wb   = sWm3 + 18432;

    int tid = threadIdx.x, w = tid >> 5, lane = tid & 31;
    for (int i = tid; i < 512;   i += blockDim.x) sWm1[i] = Wm1[i];
    for (int i = tid; i < 4096;  i += blockDim.x) sWm2[i] = Wm2[i];
    for (int i = tid; i < 18432; i += blockDim.x) sWm3[i] = Wm3[i];
    __syncthreads();

    const int perW = 512 + 512 + 1088;  // h1 + h2 + msg x2
    float* h1f  = wb + w * perW;
    float* h2f  = h1f + 512;
    float* msgB = h2f + 512;
    ull* h1u = (ull*)h1f;
    ull* h2u = (ull*)h2f;

    int nwarps = gridDim.x * EW;
    int gw = blockIdx.x * EW + w;
    const float inv_s3 = 0.57735026918962576f;

    for (int e0 = gw * EPB; e0 < Ee; e0 += nwarps * EPB) {
        // ---- layer 1 ----
        #pragma unroll
        for (int p = 0; p < NPAIR; p++) {
            float sv[2][2];
            #pragma unroll
            for (int hh = 0; hh < 2; hh++) {
                int e = e0 + 2 * p + hh;
                float rv = (lane < 8) ? radial[e * 8 + lane] : 0.f;
                float a0 = 0.f, a1 = 0.f;
                #pragma unroll
                for (int k = 0; k < 8; k++) {
                    float rk = __shfl_sync(0xffffffffu, rv, k);
                    a0 = fmaf(rk, sWm1[k * 64 + lane],      a0);
                    a1 = fmaf(rk, sWm1[k * 64 + lane + 32], a1);
                }
                sv[hh][0] = silu_f(a0);
                sv[hh][1] = silu_f(a1);
            }
            h1u[p * 64 + lane]      = pack2(sv[0][0], sv[1][0]);
            h1u[p * 64 + lane + 32] = pack2(sv[0][1], sv[1][1]);
        }
        __syncwarp();

        // ---- layer 2 ----
        {
            ull acc0[NPAIR], acc1[NPAIR];
            #pragma unroll
            for (int p = 0; p < NPAIR; p++) { acc0[p] = 0ull; acc1[p] = 0ull; }
            for (int k = 0; k < 64; k++) {
                float w0 = sWm2[k * 64 + lane];
                float w1 = sWm2[k * 64 + lane + 32];
                ull w0p = dup2(w0);
                ull w1p = dup2(w1);
                #pragma unroll
                for (int p = 0; p < NPAIR; p++) {
                    ull hp = h1u[p * 64 + k];
                    acc0[p] = fma2(hp, w0p, acc0[p]);
                    acc1[p] = fma2(hp, w1p, acc1[p]);
                }
            }
            #pragma unroll
            for (int p = 0; p < NPAIR; p++) {
                float x, y;
                unpack2(acc0[p], x, y);
                h2u[p * 64 + lane] = pack2(silu_f(x), silu_f(y));
                unpack2(acc1[p], x, y);
                h2u[p * 64 + lane + 32] = pack2(silu_f(x), silu_f(y));
            }
        }
        __syncwarp();

        // ---- layer 3 ----
        ull m2[NPAIR * 9];
        #pragma unroll
        for (int i = 0; i < NPAIR * 9; i++) m2[i] = 0ull;

        for (int k = 0; k < 64; k++) {
            ull hp[NPAIR];
            #pragma unroll
            for (int p = 0; p < NPAIR; p++) hp[p] = h2u[p * 64 + k];
            #pragma unroll
            for (int r = 0; r < 9; r++) {
                float wv = sWm3[k * 288 + lane + 32 * r];
                ull wp = dup2(wv);
                #pragma unroll
                for (int p = 0; p < NPAIR; p++)
                    m2[p * 9 + r] = fma2(hp[p], wp, m2[p * 9 + r]);
            }
        }

        // ---- messages + scatter (double-buffered msg; single syncwarp per edge) ----
        #pragma unroll
        for (int t = 0; t < EPB; t++) {
            int pp = t >> 1, hh = t & 1;
            float* msg = msgB + (t & 1) * 544;
            float mr[9];
            #pragma unroll
            for (int r = 0; r < 9; r++) {
                float lo, hi;
                unpack2(m2[pp * 9 + r], lo, hi);
                mr[r] = hh ? hi : lo;
            }
            int e = e0 + t;
            int snd = senders[e];
            int rcv = receivers[e];
            float m0  = g_s[snd * 64 + lane];
            float m1  = g_s[snd * 64 + lane + 32];
            float mv0 = g_v[snd * 96 + lane * 3];
            float mv1 = g_v[snd * 96 + lane * 3 + 1];
            float mv2 = g_v[snd * 96 + lane * 3 + 2];
            float y0  = Y0[e];
            float y10 = Y1[e * 3], y11 = Y1[e * 3 + 1], y12 = Y1[e * 3 + 2];
            float dot = (mv0 * y10 + mv1 * y11 + mv2 * y12) * inv_s3;

            msg[lane]       = m0 * mr[0];
            msg[32 + lane]  = m1 * mr[1];
            msg[64 + lane]  = m0 * y0 * mr[2];
            msg[96 + lane]  = m1 * y0 * mr[3];
            msg[128 + lane] = dot * mr[4];
            float vv5 = mr[5];
            msg[160 + lane]       = mv0 * vv5;
            msg[160 + 128 + lane] = mv1 * vv5;
            msg[160 + 256 + lane] = mv2 * vv5;
            float f6 = m0 * mr[6];
            msg[160 + 32 + lane]        = f6 * y10;
            msg[160 + 128 + 32 + lane]  = f6 * y11;
            msg[160 + 256 + 32 + lane]  = f6 * y12;
            float f7 = m1 * mr[7];
            msg[160 + 64 + lane]        = f7 * y10;
            msg[160 + 128 + 64 + lane]  = f7 * y11;
            msg[160 + 256 + 64 + lane]  = f7 * y12;
            float f8 = y0 * mr[8];
            msg[160 + 96 + lane]        = mv0 * f8;
            msg[160 + 128 + 96 + lane]  = mv1 * f8;
            msg[160 + 256 + 96 + lane]  = mv2 * f8;
            __syncwarp();

            float* aggs = g_agg_s + (long)rcv * NSs;
            float* aggv = g_agg_v + (long)rcv * (NVv * 3);
            const float4* m4 = (const float4*)msg;
            #pragma unroll
            for (int gi = 0; gi < 5; gi++) {
                int g = lane + gi * 32;
                if (g < 136) {
                    float4 vv = m4[g];
                    float* p = (g < 40) ? (aggs + 4 * g) : (aggv + 4 * (g - 40));
                    asm volatile("red.global.add.v4.f32 [%0], {%1, %2, %3, %4};"
                                 :: "l"(p), "f"(vv.x), "f"(vv.y), "f"(vv.z), "f"(vv.w)
                                 : "memory");
                }
            }
            // no trailing syncwarp: next edge writes the other msg buffer; the
            // next write-sync orders this edge's reads before its buffer reuse
        }
    }
}

// ---------------- node_kernel: full node path in one launch (proven R9 version) ----------------
// smem (floats): region0 [0, 21504) multi-use; s1s/v1s [21504, 26112); sq [26112, 26688)
#define S1OFF  21504
#define SQOFF  26112
#define NODE_SMEM_FLOATS 26688

__device__ void quantum_rows(const float* sOut, const float* sq, int row0,
                             int nrows, float* out0)
{
    int t = threadIdx.x;
    const float* sWq = sq;
    const float* cw  = sq + 512;
    const float* sw_ = sq + 536;
    const float* sWo = sq + 560;
    float bo0 = sq[568];
    int w = t >> 5, lane = t & 31;

    #pragma unroll 1
    for (int pass = 0; pass < nrows / 8; pass++) {
        int r = pass * 8 + w;
        int n = row0 + r;
        const float* srow = sOut + r * 65;
        float s_lo = srow[lane];
        float s_hi = srow[lane + 32];

        float frow[8];
        #pragma unroll
        for (int q = 0; q < 8; q++)
            frow[q] = s_lo * sWq[lane * 8 + q] + s_hi * sWq[(lane + 32) * 8 + q];
        #pragma unroll
        for (int q = 0; q < 8; q++) {
            #pragma unroll
            for (int off = 16; off > 0; off >>= 1)
                frow[q] += __shfl_xor_sync(0xffffffffu, frow[q], off);
        }

        float cs[8], sn[8];
        #pragma unroll
        for (int q = 0; q < 8; q++) {
            float a = 0.5f * frow[q];
            __sincosf(a, &sn[q], &cs[q]);
        }
        float lf = 1.f;
        #pragma unroll
        for (int j = 0; j < 5; j++) {
            int q = 4 - j;
            lf *= ((lane >> j) & 1) ? sn[q] : cs[q];
        }
        float amp[8];
        #pragma unroll
        for (int l = 0; l < 8; l++) {
            float f = lf;
            f *= (l & 4) ? sn[5] : cs[5];
            f *= (l & 2) ? sn[6] : cs[6];
            f *= (l & 1) ? sn[7] : cs[7];
            amp[l] = f;
        }

        #pragma unroll
        for (int L = 0; L < 3; L++) {
            #pragma unroll
            for (int q = 0; q < 8; q++) {
                float c = cw[L * 8 + q], s = sw_[L * 8 + q];
                const int b = 7 - q;
                if (b >= 3) {
                    const int m = 1 << (b - 3);
                    int bit = (lane >> (b - 3)) & 1;
                    #pragma unroll
                    for (int l = 0; l < 8; l++) {
                        float p = __shfl_xor_sync(0xffffffffu, amp[l], m);
                        amp[l] = bit ? fmaf(s, p, c * amp[l]) : (c * amp[l] - s * p);
                    }
                } else {
                    const int tm = 1 << b;
                    #pragma unroll
                    for (int l = 0; l < 8; l++) {
                        if (!(l & tm)) {
                            float a0 = amp[l], a1 = amp[l | tm];
                            amp[l]      = c * a0 - s * a1;
                            amp[l | tm] = fmaf(s, a0, c * a1);
                        }
                    }
                }
            }
            #pragma unroll
            for (int q = 0; q < 8; q++) {
                const int bc = 7 - q;
                const int bt = 7 - ((q + 1) & 7);
                if (bt >= 3) {
                    const int m = 1 << (bt - 3);
                    #pragma unroll
                    for (int l = 0; l < 8; l++) {
                        float p = __shfl_xor_sync(0xffffffffu, amp[l], m);
                        int ctrl = (bc >= 3) ? ((lane >> (bc - 3)) & 1) : ((l >> bc) & 1);
                        amp[l] = ctrl ? p : amp[l];
                    }
                } else {
                    const int tm = 1 << bt;
                    if (bc >= 3) {
                        int ctrl = (lane >> (bc - 3)) & 1;
                        #pragma unroll
                        for (int l = 0; l < 8; l++) {
                            if (!(l & tm)) {
                                float a = amp[l], bb = amp[l | tm];
                                amp[l]      = ctrl ? bb : a;
                                amp[l | tm] = ctrl ? a : bb;
                            }
                        }
                    } else {
                        #pragma unroll
                        for (int l = 0; l < 8; l++) {
                            if (!(l & tm) && ((l >> bc) & 1)) {
                                float tmp = amp[l];
                                amp[l] = amp[l | tm];
                                amp[l | tm] = tmp;
                            }
                        }
                    }
                }
            }
        }

        float tsum = 0.f, tb0 = 0.f, tb1 = 0.f, tb2 = 0.f;
        #pragma unroll
        for (int l = 0; l < 8; l++) {
            float p = amp[l] * amp[l];
            tsum += p;
            tb0 += (l & 1) ? -p : p;
            tb1 += (l & 2) ? -p : p;
            tb2 += (l & 4) ? -p : p;
        }
        float lanesum = 0.f;
        #pragma unroll
        for (int q = 0; q < 5; q++) {
            float sgn = ((lane >> (4 - q)) & 1) ? -1.f : 1.f;
            lanesum = fmaf(sgn * sWo[q], 1.f, lanesum);
        }
        float op = sWo[7] * tb0 + sWo[6] * tb1 + sWo[5] * tb2 + tsum * lanesum;
        #pragma unroll
        for (int o = 16; o > 0; o >>= 1)
            op += __shfl_xor_sync(0xffffffffu, op, o);
        if (lane == 0) out0[n] = op + bo0;
    }
}

__global__ void __launch_bounds__(256, 2) node_kernel(
    const float* __restrict__ Wd0, const float* __restrict__ Wd1,
    const float* __restrict__ Wt0, const float* __restrict__ Wt1,
    const float* __restrict__ x_node,
    const float* __restrict__ Wq, const float* __restrict__ wqml,
    const float* __restrict__ Wo, const float* __restrict__ bo,
    float* __restrict__ out0, float* __restrict__ outS, float* __restrict__ outV)
{
    extern __shared__ float smg[];
    float* sq = smg + SQOFF;
    int t = threadIdx.x;
    const float inv16 = 1.0f / 16.0f;

    for (int i = t; i < 512; i += 256) sq[i] = Wq[i];
    if (t < 24) {
        float ang = 0.5f * wqml[t];
        sq[512 + t] = cosf(ang);
        sq[536 + t] = sinf(ang);
    }
    if (t < 8)  sq[560 + t] = Wo[t];
    if (t == 0) sq[568] = bo[0];

    if (blockIdx.x < 128) {
        // =================== s branch: 64 nodes ===================
        int row0 = blockIdx.x * 64;
        float* sA1 = smg;              // 64 x 164
        float* sB1 = smg + 10496;      // 160 x 68
        float* s1s = smg + S1OFF;      // 64 x 68

        for (int i4 = t; i4 < 64 * 40; i4 += 256) {
            int r = i4 / 40, c4 = i4 - r * 40;
            *(float4*)(sA1 + r * 164 + c4 * 4) =
                *(const float4*)(g_agg_s + (long)(row0 + r) * 160 + c4 * 4);
        }
        for (int i4 = t; i4 < 160 * 16; i4 += 256) {
            int r = i4 >> 4, c4 = i4 & 15;
            *(float4*)(sB1 + r * 68 + c4 * 4) = *(const float4*)(Wd0 + r * 64 + c4 * 4);
        }
        __syncthreads();

        int tx = t & 15, ty = t >> 4;   // TX=16, TY=16, TM=4
        {
            ull acc[4][2];
            #pragma unroll
            for (int mi = 0; mi < 4; mi++) { acc[mi][0] = 0ull; acc[mi][1] = 0ull; }
            const float* aB = sA1 + ty * 4 * 164;
            const float* bB = sB1 + 4 * tx;
            #pragma unroll 4
            for (int k = 0; k < 160; k++) {
                ull b0 = lds64(bB + k * 68);
                ull b1 = lds64(bB + k * 68 + 2);
                #pragma unroll
                for (int mi = 0; mi < 4; mi++) {
                    ull ad = dup2(aB[mi * 164 + k]);
                    acc[mi][0] = fma2(b0, ad, acc[mi][0]);
                    acc[mi][1] = fma2(b1, ad, acc[mi][1]);
                }
            }
            #pragma unroll
            for (int mi = 0; mi < 4; mi++) {
                float v0, v1, v2, v3;
                unpack2(acc[mi][0], v0, v1);
                unpack2(acc[mi][1], v2, v3);
                *(float4*)(s1s + (ty * 4 + mi) * 68 + 4 * tx) =
                    make_float4(v0 * inv16, v1 * inv16, v2 * inv16, v3 * inv16);
            }
        }
        __syncthreads();

        // phase 2: outS = (x (x) s1) @ Wt0 + skip; expansion fused into mainloop
        float* sB2 = smg;              // 256 x 68
        for (int i4 = t; i4 < 256 * 16; i4 += 256) {
            int r = i4 >> 4, c4 = i4 & 15;
            *(float4*)(sB2 + r * 68 + c4 * 4) = *(const float4*)(Wt0 + r * 64 + c4 * 4);
        }
        float xr[4][4];
        #pragma unroll
        for (int mi = 0; mi < 4; mi++) {
            float4 xq = *(const float4*)(x_node + (row0 + ty * 4 + mi) * 4);
            xr[mi][0] = xq.x; xr[mi][1] = xq.y; xr[mi][2] = xq.z; xr[mi][3] = xq.w;
        }
        __syncthreads();

        float ov[4][4];
        {
            ull acc[4][2];
            #pragma unroll
            for (int mi = 0; mi < 4; mi++) { acc[mi][0] = 0ull; acc[mi][1] = 0ull; }
            const float* bB = sB2 + 4 * tx;
            const float* s1B = s1s + ty * 4 * 68;
            #pragma unroll 1
            for (int a = 0; a < 4; a++) {
                const float* bA = bB + a * 64 * 68;
                #pragma unroll 4
                for (int c = 0; c < 64; c++) {
                    ull b0 = lds64(bA + c * 68);
                    ull b1 = lds64(bA + c * 68 + 2);
                    #pragma unroll
                    for (int mi = 0; mi < 4; mi++) {
                        float sv = s1B[mi * 68 + c];
                        ull ad = dup2(xr[mi][a] * sv);
                        acc[mi][0] = fma2(b0, ad, acc[mi][0]);
                        acc[mi][1] = fma2(b1, ad, acc[mi][1]);
                    }
                }
            }
            #pragma unroll
            for (int mi = 0; mi < 4; mi++) {
                int row = row0 + ty * 4 + mi;
                float v0, v1, v2, v3;
                unpack2(acc[mi][0], v0, v1);
                unpack2(acc[mi][1], v2, v3);
                float4 sk = *(const float4*)(g_skip_s + (long)row * 64 + 4 * tx);
                ov[mi][0] = v0 + sk.x; ov[mi][1] = v1 + sk.y;
                ov[mi][2] = v2 + sk.z; ov[mi][3] = v3 + sk.w;
            }
        }
        __syncthreads();                 // sB2 dead
        float* sOut = smg;               // 64 x 65
        #pragma unroll
        for (int mi = 0; mi < 4; mi++) {
            int r = ty * 4 + mi;
            int row = row0 + r;
            *(float4*)(outS + (long)row * 64 + 4 * tx) =
                make_float4(ov[mi][0], ov[mi][1], ov[mi][2], ov[mi][3]);
            sOut[r * 65 + 4 * tx]     = ov[mi][0];
            sOut[r * 65 + 4 * tx + 1] = ov[mi][1];
            sOut[r * 65 + 4 * tx + 2] = ov[mi][2];
            sOut[r * 65 + 4 * tx + 3] = ov[mi][3];
        }
        __syncthreads();

        quantum_rows(sOut, sq, row0, 64, out0);
    } else {
        // =================== v branch: 128 rows of (3n+ii) ===================
        int row0 = (blockIdx.x - 128) * 128;
        float* sA  = smg;              // 128 x 132
        float* sB1 = smg + 16896;      // 128 x 36
        float* v1s = smg + S1OFF;      // 128 x 36

        for (int i4 = t; i4 < 128 * 32; i4 += 256) {
            int r = i4 >> 5, c4 = i4 & 31;
            *(float4*)(sA + r * 132 + c4 * 4) =
                *(const float4*)(g_agg_v + (long)(row0 + r) * 128 + c4 * 4);
        }
        for (int i4 = t; i4 < 128 * 8; i4 += 256) {
            int r = i4 >> 3, c4 = i4 & 7;
            *(float4*)(sB1 + r * 36 + c4 * 4) = *(const float4*)(Wd1 + r * 32 + c4 * 4);
        }
        __syncthreads();

        int tx = t & 7, ty = t >> 3;    // TX=8, TY=32, TM=4
        {
            ull acc[4][2];
            #pragma unroll
            for (int mi = 0; mi < 4; mi++) { acc[mi][0] = 0ull; acc[mi][1] = 0ull; }
            const float* aB = sA + ty * 4 * 132;
            const float* bB = sB1 + 4 * tx;
            #pragma unroll 4
            for (int k = 0; k < 128; k++) {
                ull b0 = lds64(bB + k * 36);
                ull b1 = lds64(bB + k * 36 + 2);
                #pragma unroll
                for (int mi = 0; mi < 4; mi++) {
                    ull ad = dup2(aB[mi * 132 + k]);
                    acc[mi][0] = fma2(b0, ad, acc[mi][0]);
                    acc[mi][1] = fma2(b1, ad, acc[mi][1]);
                }
            }
            #pragma unroll
            for (int mi = 0; mi < 4; mi++) {
                float v0, v1, v2, v3;
                unpack2(acc[mi][0], v0, v1);
                unpack2(acc[mi][1], v2, v3);
                *(float4*)(v1s + (ty * 4 + mi) * 36 + 4 * tx) =
                    make_float4(v0 * inv16, v1 * inv16, v2 * inv16, v3 * inv16);
            }
        }
        __syncthreads();

        float* sB2 = smg;              // 128 x 36
        for (int i4 = t; i4 < 128 * 8; i4 += 256) {
            int r = i4 >> 3, c4 = i4 & 7;
            *(float4*)(sB2 + r * 36 + c4 * 4) = *(const float4*)(Wt1 + r * 32 + c4 * 4);
        }
        float xr[4][4];
        #pragma unroll
        for (int mi = 0; mi < 4; mi++) {
            int rr = row0 + ty * 4 + mi;
            float4 xq = *(const float4*)(x_node + (rr / 3) * 4);
            xr[mi][0] = xq.x; xr[mi][1] = xq.y; xr[mi][2] = xq.z; xr[mi][3] = xq.w;
        }
        __syncthreads();

        {
            ull acc[4][2];
            #pragma unroll
            for (int mi = 0; mi < 4; mi++) { acc[mi][0] = 0ull; acc[mi][1] = 0ull; }
            const float* bB = sB2 + 4 * tx;
            const float* v1B = v1s + ty * 4 * 36;
            #pragma unroll 1
            for (int a = 0; a < 4; a++) {
                const float* bA = bB + a * 32 * 36;
                #pragma unroll 4
                for (int c = 0; c < 32; c++) {
                    ull b0 = lds64(bA + c * 36);
                    ull b1 = lds64(bA + c * 36 + 2);
                    #pragma unroll
                    for (int mi = 0; mi < 4; mi++) {
                        float sv = v1B[mi * 36 + c];
                        ull ad = dup2(xr[mi][a] * sv);
                        acc[mi][0] = fma2(b0, ad, acc[mi][0]);
                        acc[mi][1] = fma2(b1, ad, acc[mi][1]);
                    }
                }
            }
            #pragma unroll
            for (int mi = 0; mi < 4; mi++) {
                int row = row0 + ty * 4 + mi;
                float vv[4];
                unpack2(acc[mi][0], vv[0], vv[1]);
                unpack2(acc[mi][1], vv[2], vv[3]);
                int n = row / 3, ii = row - 3 * n;
                #pragma unroll
                for (int j = 0; j < 4; j++) {
                    int c = 4 * tx + j;
                    outV[(long)n * 96 + c * 3 + ii] =
                        vv[j] + g_skip_v[(long)n * 96 + c * 3 + ii];
                }
            }
        }
    }
}

// ---------------- launch ----------------
extern "C" void kernel_launch(void* const* d_in, const int* in_sizes, int n_in,
                              void* d_out, int out_size) {
    const float* s_in     = (const float*)d_in[0];
    const float* v_in     = (const float*)d_in[1];
    const float* x_node   = (const float*)d_in[2];
    const float* radial   = (const float*)d_in[3];
    const float* Y0       = (const float*)d_in[4];
    const float* Y1       = (const float*)d_in[5];
    const int*   species  = (const int*)d_in[6];
    const int*   senders  = (const int*)d_in[7];
    const int*   receivers= (const int*)d_in[8];
    const float* Wskip0   = (const float*)d_in[9];
    const float* Wskip1   = (const float*)d_in[10];
    const float* Wu0      = (const float*)d_in[11];
    const float* Wu1      = (const float*)d_in[12];
    const float* Wm1      = (const float*)d_in[13];
    const float* Wm2      = (const float*)d_in[14];
    const float* Wm3      = (const float*)d_in[15];
    const float* Wd0      = (const float*)d_in[16];
    const float* Wd1      = (const float*)d_in[17];
    const float* Wt0      = (const float*)d_in[18];
    const float* Wt1      = (const float*)d_in[19];
    const float* Wq       = (const float*)d_in[20];
    const float* wqml     = (const float*)d_in[21];
    const float* Wo       = (const float*)d_in[22];
    const float* bo       = (const float*)d_in[23];

    float* out0 = (float*)d_out;
    float* outS = out0 + Nn;
    float* outV = outS + Nn * C0;

    static bool attr_done = false;
    size_t smem_pre  = PRE_SMEM_FLOATS * sizeof(float);                    // ~112.6 KB
    size_t smem_edge = (512 + 4096 + 18432 + EW * 2112) * sizeof(float);   // ~222 KB
    size_t smem_node = NODE_SMEM_FLOATS * sizeof(float);   // ~106.8 KB -> 2 blocks/SM
    if (!attr_done) {
        cudaFuncSetAttribute(node_pre_kernel, cudaFuncAttributeMaxDynamicSharedMemorySize, (int)smem_pre);
        cudaFuncSetAttribute(edge_kernel,     cudaFuncAttributeMaxDynamicSharedMemorySize, (int)smem_edge);
        cudaFuncSetAttribute(node_kernel,     cudaFuncAttributeMaxDynamicSharedMemorySize, (int)smem_node);
        attr_done = true;
    }

    node_pre_kernel<<<296, 256, smem_pre>>>(s_in, v_in, species, Wskip0, Wskip1, Wu0, Wu1);
    edge_kernel<<<148, 32 * EW, smem_edge>>>(radial, Y0, Y1, senders, receivers, Wm1, Wm2, Wm3);
    node_kernel<<<320, 256, smem_node>>>(Wd0, Wd1, Wt0, Wt1, x_node, Wq, wqml, Wo, bo,
                                         out0, outS, outV);
}

// round 16
// speedup vs baseline: 1.0940x; 1.0548x over previous
#include <cuda_runtime.h>
#include <math.h>

#define Nn 8192
#define Ee 131072
#define C0 64
#define C1 32
#define NSs 160     // 2*C0 + C1
#define NVv 128     // C0 + 2*C1
#define EPB 8       // edges per warp batch (edge kernel)
#define NPAIR 4     // EPB/2
#define EW 16       // warps per edge block (512 threads — proven config)

typedef unsigned long long ull;

// ---------------- static device scratch ----------------
__device__ float g_s[Nn * C0];
__device__ float g_v[Nn * C1 * 3];
__device__ float g_skip_s[Nn * C0];
__device__ float g_skip_v[Nn * C1 * 3];
__device__ float g_agg_s[Nn * NSs];
__device__ float g_agg_v[Nn * 3 * NVv];  // [n][ii][c]  (component-major)

__device__ __forceinline__ float silu_f(float x) {
    return __fdividef(x, 1.0f + __expf(-x));
}

// packed fp32x2 helpers (sm_100a): bit-exact dual fp32 FMA
__device__ __forceinline__ ull pack2(float x, float y) {
    ull r; asm("mov.b64 %0, {%1, %2};" : "=l"(r) : "f"(x), "f"(y)); return r;
}
__device__ __forceinline__ void unpack2(ull v, float& x, float& y) {
    asm("mov.b64 {%0, %1}, %2;" : "=f"(x), "=f"(y) : "l"(v));
}
__device__ __forceinline__ ull fma2(ull a, ull b, ull c) {
    ull d; asm("fma.rn.f32x2 %0, %1, %2, %3;" : "=l"(d) : "l"(a), "l"(b), "l"(c)); return d;
}
__device__ __forceinline__ ull dup2(float x) { return pack2(x, x); }
__device__ __forceinline__ ull lds64(const float* p) { return *(const ull*)p; }

// ---------------- kernel 1: node pre — node-paired fp32x2, 512 threads, grid 148 ----------------
#define PRE_SMEM_FLOATS (25600 + 16 * 320)

__global__ void __launch_bounds__(512) node_pre_kernel(
    const float* __restrict__ s_in, const float* __restrict__ v_in,
    const int* __restrict__ species,
    const float* __restrict__ Wskip0, const float* __restrict__ Wskip1,
    const float* __restrict__ Wu0, const float* __restrict__ Wu1)
{
    extern __shared__ float sm[];
    float* sWu0 = sm;                  // 4096
    float* sWu1 = sWu0 + 4096;         // 1024
    float* sWs0 = sWu1 + 1024;         // 16384
    float* sWs1 = sWs0 + 16384;        // 4096
    float* bufs = sWs1 + 4096;         // 16 warps * 320

    int tid = threadIdx.x;

    // zero aggregation buffers (kernel boundary orders this before edge_kernel)
    {
        int gt = blockIdx.x * 512 + tid;
        int gstride = gridDim.x * 512;
        float4 z4 = make_float4(0.f, 0.f, 0.f, 0.f);
        float4* az = (float4*)g_agg_s;
        for (int j = gt; j < Nn * NSs / 4; j += gstride) az[j] = z4;
        float4* bz = (float4*)g_agg_v;
        for (int j = gt; j < Nn * 3 * NVv / 4; j += gstride) bz[j] = z4;
    }

    for (int i = tid; i < 4096;  i += blockDim.x) sWu0[i] = Wu0[i];
    for (int i = tid; i < 1024;  i += blockDim.x) sWu1[i] = Wu1[i];
    for (int i = tid; i < 16384; i += blockDim.x) sWs0[i] = Wskip0[i];
    for (int i = tid; i < 4096;  i += blockDim.x) sWs1[i] = Wskip1[i];
    __syncthreads();

    int w = tid >> 5, lane = tid & 31;
    ull* sb2 = (ull*)(bufs + w * 320);      // 64 ull
    ull* vb2 = sb2 + 64;                    // 96 ull
    int warpsTotal = gridDim.x * 16;

    for (int p = blockIdx.x * 16 + w; p < Nn / 2; p += warpsTotal) {
        int n0 = 2 * p, n1 = n0 + 1;
        sb2[lane]      = pack2(s_in[n0 * 64 + lane],      s_in[n1 * 64 + lane]);
        sb2[lane + 32] = pack2(s_in[n0 * 64 + lane + 32], s_in[n1 * 64 + lane + 32]);
        vb2[lane]      = pack2(v_in[n0 * 96 + lane],      v_in[n1 * 96 + lane]);
        vb2[lane + 32] = pack2(v_in[n0 * 96 + lane + 32], v_in[n1 * 96 + lane + 32]);
        vb2[lane + 64] = pack2(v_in[n0 * 96 + lane + 64], v_in[n1 * 96 + lane + 64]);
        __syncwarp();
        int sp0 = species[n0];
        int sp1 = species[n1];
        const float* W0a = sWs0 + sp0 * 4096;
        const float* W0b = sWs0 + sp1 * 4096;
        const float* W1a = sWs1 + sp0 * 1024;
        const float* W1b = sWs1 + sp1 * 1024;

        ull aU0 = 0ull, aU1 = 0ull, aS0 = 0ull, aS1 = 0ull;
        #pragma unroll 8
        for (int c = 0; c < 64; c++) {
            ull xp = sb2[c];
            aU0 = fma2(xp, dup2(sWu0[c * 64 + lane]),      aU0);
            aU1 = fma2(xp, dup2(sWu0[c * 64 + lane + 32]), aU1);
            aS0 = fma2(xp, pack2(W0a[c * 64 + lane],      W0b[c * 64 + lane]),      aS0);
            aS1 = fma2(xp, pack2(W0a[c * 64 + lane + 32], W0b[c * 64 + lane + 32]), aS1);
        }
        {
            float lo, hi;
            unpack2(aU0, lo, hi);
            g_s[n0 * 64 + lane] = lo; g_s[n1 * 64 + lane] = hi;
            unpack2(aU1, lo, hi);
            g_s[n0 * 64 + lane + 32] = lo; g_s[n1 * 64 + lane + 32] = hi;
            unpack2(aS0, lo, hi);
            g_skip_s[n0 * 64 + lane] = lo; g_skip_s[n1 * 64 + lane] = hi;
            unpack2(aS1, lo, hi);
            g_skip_s[n0 * 64 + lane + 32] = lo; g_skip_s[n1 * 64 + lane + 32] = hi;
        }

        ull aV0 = 0ull, aV1 = 0ull, aV2 = 0ull, aK0 = 0ull, aK1 = 0ull, aK2 = 0ull;
        #pragma unroll 8
        for (int c = 0; c < 32; c++) {
            float wu = sWu1[c * 32 + lane];
            ull wup = dup2(wu);
            ull wkp = pack2(W1a[c * 32 + lane], W1b[c * 32 + lane]);
            ull x0 = vb2[c * 3], x1 = vb2[c * 3 + 1], x2 = vb2[c * 3 + 2];
            aV0 = fma2(x0, wup, aV0); aV1 = fma2(x1, wup, aV1); aV2 = fma2(x2, wup, aV2);
            aK0 = fma2(x0, wkp, aK0); aK1 = fma2(x1, wkp, aK1); aK2 = fma2(x2, wkp, aK2);
        }
        {
            float lo, hi;
            unpack2(aV0, lo, hi);
            g_v[n0 * 96 + lane * 3] = lo; g_v[n1 * 96 + lane * 3] = hi;
            unpack2(aV1, lo, hi);
            g_v[n0 * 96 + lane * 3 + 1] = lo; g_v[n1 * 96 + lane * 3 + 1] = hi;
            unpack2(aV2, lo, hi);
            g_v[n0 * 96 + lane * 3 + 2] = lo; g_v[n1 * 96 + lane * 3 + 2] = hi;
            unpack2(aK0, lo, hi);
            g_skip_v[n0 * 96 + lane * 3] = lo; g_skip_v[n1 * 96 + lane * 3] = hi;
            unpack2(aK1, lo, hi);
            g_skip_v[n0 * 96 + lane * 3 + 1] = lo; g_skip_v[n1 * 96 + lane * 3 + 1] = hi;
            unpack2(aK2, lo, hi);
            g_skip_v[n0 * 96 + lane * 3 + 2] = lo; g_skip_v[n1 * 96 + lane * 3 + 2] = hi;
        }
        __syncwarp();
    }
}

// ---------------- kernel 2: fused edge MLP + scatter — pair-packed weights, dbuf msg ----------------
// weight layouts (repacked at staging):
//   sWm1p[k*66 + 2*l + h]   <- Wm1[k*64 + h*32 + l]        (8 rows)
//   sWm2p[k*66 + 2*l + h]   <- Wm2[k*64 + h*32 + l]        (64 rows)
//   sWm3p[k*292 + (r>>1)*64 + 2*l + (r&1)] <- Wm3[k*288 + r*32 + l]  (r<8)
//   sWm3p[k*292 + 256 + l]                 <- Wm3[k*288 + 256 + l]   (r=8)
__global__ void __launch_bounds__(32 * EW) edge_kernel(
    const float* __restrict__ radial, const float* __restrict__ Y0,
    const float* __restrict__ Y1,
    const int* __restrict__ senders, const int* __restrict__ receivers,
    const float* __restrict__ Wm1, const float* __restrict__ Wm2,
    const float* __restrict__ Wm3)
{
    extern __shared__ float sm[];
    float* sWm1p = sm;                 // 528
    float* sWm2p = sm + 528;           // 4224
    float* sWm3p = sm + 4752;          // 18688
    float* wb    = sm + 23440;

    int tid = threadIdx.x, w = tid >> 5, lane = tid & 31;
    for (int i = tid; i < 512; i += blockDim.x) {
        int k = i >> 6, c = i & 63;
        sWm1p[k * 66 + 2 * (c & 31) + (c >> 5)] = Wm1[i];
    }
    for (int i = tid; i < 4096; i += blockDim.x) {
        int k = i >> 6, c = i & 63;
        sWm2p[k * 66 + 2 * (c & 31) + (c >> 5)] = Wm2[i];
    }
    for (int i = tid; i < 18432; i += blockDim.x) {
        int k = i / 288, c = i - k * 288;
        int r = c >> 5, l = c & 31;
        int dst = (r < 8) ? (k * 292 + (r >> 1) * 64 + 2 * l + (r & 1))
                          : (k * 292 + 256 + l);
        sWm3p[dst] = Wm3[i];
    }
    __syncthreads();

    const int perW = 512 + 512 + 1088;  // h1 + h2 + msg x2
    float* h1f  = wb + w * perW;
    float* h2f  = h1f + 512;
    float* msgB = h2f + 512;
    ull* h1u = (ull*)h1f;
    ull* h2u = (ull*)h2f;

    int nwarps = gridDim.x * EW;
    int gw = blockIdx.x * EW + w;
    const float inv_s3 = 0.57735026918962576f;

    for (int e0 = gw * EPB; e0 < Ee; e0 += nwarps * EPB) {
        // ---- layer 1 ----
        #pragma unroll
        for (int p = 0; p < NPAIR; p++) {
            float sv[2][2];
            #pragma unroll
            for (int hh = 0; hh < 2; hh++) {
                int e = e0 + 2 * p + hh;
                float rv = (lane < 8) ? radial[e * 8 + lane] : 0.f;
                float a0 = 0.f, a1 = 0.f;
                #pragma unroll
                for (int k = 0; k < 8; k++) {
                    float rk = __shfl_sync(0xffffffffu, rv, k);
                    ull wp = lds64(sWm1p + k * 66 + 2 * lane);
                    float w0l, w1l; unpack2(wp, w0l, w1l);
                    a0 = fmaf(rk, w0l, a0);
                    a1 = fmaf(rk, w1l, a1);
                }
                sv[hh][0] = silu_f(a0);
                sv[hh][1] = silu_f(a1);
            }
            h1u[p * 64 + lane]      = pack2(sv[0][0], sv[1][0]);
            h1u[p * 64 + lane + 32] = pack2(sv[0][1], sv[1][1]);
        }
        __syncwarp();

        // ---- layer 2 ----
        {
            ull acc0[NPAIR], acc1[NPAIR];
            #pragma unroll
            for (int p = 0; p < NPAIR; p++) { acc0[p] = 0ull; acc1[p] = 0ull; }
            for (int k = 0; k < 64; k++) {
                ull wp = lds64(sWm2p + k * 66 + 2 * lane);
                float w0l, w1l; unpack2(wp, w0l, w1l);
                ull w0p = dup2(w0l);
                ull w1p = dup2(w1l);
                #pragma unroll
                for (int p = 0; p < NPAIR; p++) {
                    ull hp = h1u[p * 64 + k];
                    acc0[p] = fma2(hp, w0p, acc0[p]);
                    acc1[p] = fma2(hp, w1p, acc1[p]);
                }
            }
            #pragma unroll
            for (int p = 0; p < NPAIR; p++) {
                float x, y;
                unpack2(acc0[p], x, y);
                h2u[p * 64 + lane] = pack2(silu_f(x), silu_f(y));
                unpack2(acc1[p], x, y);
                h2u[p * 64 + lane + 32] = pack2(silu_f(x), silu_f(y));
            }
        }
        __syncwarp();

        // ---- layer 3 (pair-packed weights) ----
        ull m2[NPAIR * 9];
        #pragma unroll
        for (int i = 0; i < NPAIR * 9; i++) m2[i] = 0ull;

        for (int k = 0; k < 64; k++) {
            ull hp[NPAIR];
            #pragma unroll
            for (int p = 0; p < NPAIR; p++) hp[p] = h2u[p * 64 + k];
            const float* wk = sWm3p + k * 292;
            #pragma unroll
            for (int r2 = 0; r2 < 4; r2++) {
                ull wpair = lds64(wk + r2 * 64 + 2 * lane);
                float wa, wb2; unpack2(wpair, wa, wb2);
                ull wpa = dup2(wa);
                ull wpb = dup2(wb2);
                #pragma unroll
                for (int p = 0; p < NPAIR; p++) {
                    m2[p * 9 + 2 * r2]     = fma2(hp[p], wpa, m2[p * 9 + 2 * r2]);
                    m2[p * 9 + 2 * r2 + 1] = fma2(hp[p], wpb, m2[p * 9 + 2 * r2 + 1]);
                }
            }
            ull wp8 = dup2(wk[256 + lane]);
            #pragma unroll
            for (int p = 0; p < NPAIR; p++)
                m2[p * 9 + 8] = fma2(hp[p], wp8, m2[p * 9 + 8]);
        }

        // ---- messages + scatter (double-buffered msg; single syncwarp per edge) ----
        #pragma unroll
        for (int t = 0; t < EPB; t++) {
            int pp = t >> 1, hh = t & 1;
            float* msg = msgB + (t & 1) * 544;
            float mr[9];
            #pragma unroll
            for (int r = 0; r < 9; r++) {
                float lo, hi;
                unpack2(m2[pp * 9 + r], lo, hi);
                mr[r] = hh ? hi : lo;
            }
            int e = e0 + t;
            int snd = senders[e];
            int rcv = receivers[e];
            float m0  = g_s[snd * 64 + lane];
            float m1  = g_s[snd * 64 + lane + 32];
            float mv0 = g_v[snd * 96 + lane * 3];
            float mv1 = g_v[snd * 96 + lane * 3 + 1];
            float mv2 = g_v[snd * 96 + lane * 3 + 2];
            float y0  = Y0[e];
            float y10 = Y1[e * 3], y11 = Y1[e * 3 + 1], y12 = Y1[e * 3 + 2];
            float dot = (mv0 * y10 + mv1 * y11 + mv2 * y12) * inv_s3;

            msg[lane]       = m0 * mr[0];
            msg[32 + lane]  = m1 * mr[1];
            msg[64 + lane]  = m0 * y0 * mr[2];
            msg[96 + lane]  = m1 * y0 * mr[3];
            msg[128 + lane] = dot * mr[4];
            float vv5 = mr[5];
            msg[160 + lane]       = mv0 * vv5;
            msg[160 + 128 + lane] = mv1 * vv5;
            msg[160 + 256 + lane] = mv2 * vv5;
            float f6 = m0 * mr[6];
            msg[160 + 32 + lane]        = f6 * y10;
            msg[160 + 128 + 32 + lane]  = f6 * y11;
            msg[160 + 256 + 32 + lane]  = f6 * y12;
            float f7 = m1 * mr[7];
            msg[160 + 64 + lane]        = f7 * y10;
            msg[160 + 128 + 64 + lane]  = f7 * y11;
            msg[160 + 256 + 64 + lane]  = f7 * y12;
            float f8 = y0 * mr[8];
            msg[160 + 96 + lane]        = mv0 * f8;
            msg[160 + 128 + 96 + lane]  = mv1 * f8;
            msg[160 + 256 + 96 + lane]  = mv2 * f8;
            __syncwarp();

            float* aggs = g_agg_s + (long)rcv * NSs;
            float* aggv = g_agg_v + (long)rcv * (NVv * 3);
            const float4* m4 = (const float4*)msg;
            #pragma unroll
            for (int gi = 0; gi < 5; gi++) {
                int g = lane + gi * 32;
                if (g < 136) {
                    float4 vv = m4[g];
                    float* p = (g < 40) ? (aggs + 4 * g) : (aggv + 4 * (g - 40));
                    asm volatile("red.global.add.v4.f32 [%0], {%1, %2, %3, %4};"
                                 :: "l"(p), "f"(vv.x), "f"(vv.y), "f"(vv.z), "f"(vv.w)
                                 : "memory");
                }
            }
        }
    }
}

// ---------------- node_kernel: full node path in one launch (proven R9 version) ----------------
// smem (floats): region0 [0, 21504) multi-use; s1s/v1s [21504, 26112); sq [26112, 26688)
#define S1OFF  21504
#define SQOFF  26112
#define NODE_SMEM_FLOATS 26688

__device__ void quantum_rows(const float* sOut, const float* sq, int row0,
                             int nrows, float* out0)
{
    int t = threadIdx.x;
    const float* sWq = sq;
    const float* cw  = sq + 512;
    const float* sw_ = sq + 536;
    const float* sWo = sq + 560;
    float bo0 = sq[568];
    int w = t >> 5, lane = t & 31;

    #pragma unroll 1
    for (int pass = 0; pass < nrows / 8; pass++) {
        int r = pass * 8 + w;
        int n = row0 + r;
        const float* srow = sOut + r * 65;
        float s_lo = srow[lane];
        float s_hi = srow[lane + 32];

        float frow[8];
        #pragma unroll
        for (int q = 0; q < 8; q++)
            frow[q] = s_lo * sWq[lane * 8 + q] + s_hi * sWq[(lane + 32) * 8 + q];
        #pragma unroll
        for (int q = 0; q < 8; q++) {
            #pragma unroll
            for (int off = 16; off > 0; off >>= 1)
                frow[q] += __shfl_xor_sync(0xffffffffu, frow[q], off);
        }

        float cs[8], sn[8];
        #pragma unroll
        for (int q = 0; q < 8; q++) {
            float a = 0.5f * frow[q];
            __sincosf(a, &sn[q], &cs[q]);
        }
        float lf = 1.f;
        #pragma unroll
        for (int j = 0; j < 5; j++) {
            int q = 4 - j;
            lf *= ((lane >> j) & 1) ? sn[q] : cs[q];
        }
        float amp[8];
        #pragma unroll
        for (int l = 0; l < 8; l++) {
            float f = lf;
            f *= (l & 4) ? sn[5] : cs[5];
            f *= (l & 2) ? sn[6] : cs[6];
            f *= (l & 1) ? sn[7] : cs[7];
            amp[l] = f;
        }

        #pragma unroll
        for (int L = 0; L < 3; L++) {
            #pragma unroll
            for (int q = 0; q < 8; q++) {
                float c = cw[L * 8 + q], s = sw_[L * 8 + q];
                const int b = 7 - q;
                if (b >= 3) {
                    const int m = 1 << (b - 3);
                    int bit = (lane >> (b - 3)) & 1;
                    #pragma unroll
                    for (int l = 0; l < 8; l++) {
                        float p = __shfl_xor_sync(0xffffffffu, amp[l], m);
                        amp[l] = bit ? fmaf(s, p, c * amp[l]) : (c * amp[l] - s * p);
                    }
                } else {
                    const int tm = 1 << b;
                    #pragma unroll
                    for (int l = 0; l < 8; l++) {
                        if (!(l & tm)) {
                            float a0 = amp[l], a1 = amp[l | tm];
                            amp[l]      = c * a0 - s * a1;
                            amp[l | tm] = fmaf(s, a0, c * a1);
                        }
                    }
                }
            }
            #pragma unroll
            for (int q = 0; q < 8; q++) {
                const int bc = 7 - q;
                const int bt = 7 - ((q + 1) & 7);
                if (bt >= 3) {
                    const int m = 1 << (bt - 3);
                    #pragma unroll
                    for (int l = 0; l < 8; l++) {
                        float p = __shfl_xor_sync(0xffffffffu, amp[l], m);
                        int ctrl = (bc >= 3) ? ((lane >> (bc - 3)) & 1) : ((l >> bc) & 1);
                        amp[l] = ctrl ? p : amp[l];
                    }
                } else {
                    const int tm = 1 << bt;
                    if (bc >= 3) {
                        int ctrl = (lane >> (bc - 3)) & 1;
                        #pragma unroll
                        for (int l = 0; l < 8; l++) {
                            if (!(l & tm)) {
                                float a = amp[l], bb = amp[l | tm];
                                amp[l]      = ctrl ? bb : a;
                                amp[l | tm] = ctrl ? a : bb;
                            }
                        }
                    } else {
                        #pragma unroll
                        for (int l = 0; l < 8; l++) {
                            if (!(l & tm) && ((l >> bc) & 1)) {
                                float tmp = amp[l];
                                amp[l] = amp[l | tm];
                                amp[l | tm] = tmp;
                            }
                        }
                    }
                }
            }
        }

        float tsum = 0.f, tb0 = 0.f, tb1 = 0.f, tb2 = 0.f;
        #pragma unroll
        for (int l = 0; l < 8; l++) {
            float p = amp[l] * amp[l];
            tsum += p;
            tb0 += (l & 1) ? -p : p;
            tb1 += (l & 2) ? -p : p;
            tb2 += (l & 4) ? -p : p;
        }
        float lanesum = 0.f;
        #pragma unroll
        for (int q = 0; q < 5; q++) {
            float sgn = ((lane >> (4 - q)) & 1) ? -1.f : 1.f;
            lanesum = fmaf(sgn * sWo[q], 1.f, lanesum);
        }
        float op = sWo[7] * tb0 + sWo[6] * tb1 + sWo[5] * tb2 + tsum * lanesum;
        #pragma unroll
        for (int o = 16; o > 0; o >>= 1)
            op += __shfl_xor_sync(0xffffffffu, op, o);
        if (lane == 0) out0[n] = op + bo0;
    }
}

__global__ void __launch_bounds__(256, 2) node_kernel(
    const float* __restrict__ Wd0, const float* __restrict__ Wd1,
    const float* __restrict__ Wt0, const float* __restrict__ Wt1,
    const float* __restrict__ x_node,
    const float* __restrict__ Wq, const float* __restrict__ wqml,
    const float* __restrict__ Wo, const float* __restrict__ bo,
    float* __restrict__ out0, float* __restrict__ outS, float* __restrict__ outV)
{
    extern __shared__ float smg[];
    float* sq = smg + SQOFF;
    int t = threadIdx.x;
    const float inv16 = 1.0f / 16.0f;

    for (int i = t; i < 512; i += 256) sq[i] = Wq[i];
    if (t < 24) {
        float ang = 0.5f * wqml[t];
        sq[512 + t] = cosf(ang);
        sq[536 + t] = sinf(ang);
    }
    if (t < 8)  sq[560 + t] = Wo[t];
    if (t == 0) sq[568] = bo[0];

    if (blockIdx.x < 128) {
        // =================== s branch: 64 nodes ===================
        int row0 = blockIdx.x * 64;
        float* sA1 = smg;              // 64 x 164
        float* sB1 = smg + 10496;      // 160 x 68
        float* s1s = smg + S1OFF;      // 64 x 68

        for (int i4 = t; i4 < 64 * 40; i4 += 256) {
            int r = i4 / 40, c4 = i4 - r * 40;
            *(float4*)(sA1 + r * 164 + c4 * 4) =
                *(const float4*)(g_agg_s + (long)(row0 + r) * 160 + c4 * 4);
        }
        for (int i4 = t; i4 < 160 * 16; i4 += 256) {
            int r = i4 >> 4, c4 = i4 & 15;
            *(float4*)(sB1 + r * 68 + c4 * 4) = *(const float4*)(Wd0 + r * 64 + c4 * 4);
        }
        __syncthreads();

        int tx = t & 15, ty = t >> 4;   // TX=16, TY=16, TM=4
        {
            ull acc[4][2];
            #pragma unroll
            for (int mi = 0; mi < 4; mi++) { acc[mi][0] = 0ull; acc[mi][1] = 0ull; }
            const float* aB = sA1 + ty * 4 * 164;
            const float* bB = sB1 + 4 * tx;
            #pragma unroll 4
            for (int k = 0; k < 160; k++) {
                ull b0 = lds64(bB + k * 68);
                ull b1 = lds64(bB + k * 68 + 2);
                #pragma unroll
                for (int mi = 0; mi < 4; mi++) {
                    ull ad = dup2(aB[mi * 164 + k]);
                    acc[mi][0] = fma2(b0, ad, acc[mi][0]);
                    acc[mi][1] = fma2(b1, ad, acc[mi][1]);
                }
            }
            #pragma unroll
            for (int mi = 0; mi < 4; mi++) {
                float v0, v1, v2, v3;
                unpack2(acc[mi][0], v0, v1);
                unpack2(acc[mi][1], v2, v3);
                *(float4*)(s1s + (ty * 4 + mi) * 68 + 4 * tx) =
                    make_float4(v0 * inv16, v1 * inv16, v2 * inv16, v3 * inv16);
            }
        }
        __syncthreads();

        // phase 2: outS = (x (x) s1) @ Wt0 + skip; expansion fused into mainloop
        float* sB2 = smg;              // 256 x 68
        for (int i4 = t; i4 < 256 * 16; i4 += 256) {
            int r = i4 >> 4, c4 = i4 & 15;
            *(float4*)(sB2 + r * 68 + c4 * 4) = *(const float4*)(Wt0 + r * 64 + c4 * 4);
        }
        float xr[4][4];
        #pragma unroll
        for (int mi = 0; mi < 4; mi++) {
            float4 xq = *(const float4*)(x_node + (row0 + ty * 4 + mi) * 4);
            xr[mi][0] = xq.x; xr[mi][1] = xq.y; xr[mi][2] = xq.z; xr[mi][3] = xq.w;
        }
        __syncthreads();

        float ov[4][4];
        {
            ull acc[4][2];
            #pragma unroll
            for (int mi = 0; mi < 4; mi++) { acc[mi][0] = 0ull; acc[mi][1] = 0ull; }
            const float* bB = sB2 + 4 * tx;
            const float* s1B = s1s + ty * 4 * 68;
            #pragma unroll 1
            for (int a = 0; a < 4; a++) {
                const float* bA = bB + a * 64 * 68;
                #pragma unroll 4
                for (int c = 0; c < 64; c++) {
                    ull b0 = lds64(bA + c * 68);
                    ull b1 = lds64(bA + c * 68 + 2);
                    #pragma unroll
                    for (int mi = 0; mi < 4; mi++) {
                        float sv = s1B[mi * 68 + c];
                        ull ad = dup2(xr[mi][a] * sv);
                        acc[mi][0] = fma2(b0, ad, acc[mi][0]);
                        acc[mi][1] = fma2(b1, ad, acc[mi][1]);
                    }
                }
            }
            #pragma unroll
            for (int mi = 0; mi < 4; mi++) {
                int row = row0 + ty * 4 + mi;
                float v0, v1, v2, v3;
                unpack2(acc[mi][0], v0, v1);
                unpack2(acc[mi][1], v2, v3);
                float4 sk = *(const float4*)(g_skip_s + (long)row * 64 + 4 * tx);
                ov[mi][0] = v0 + sk.x; ov[mi][1] = v1 + sk.y;
                ov[mi][2] = v2 + sk.z; ov[mi][3] = v3 + sk.w;
            }
        }
        __syncthreads();                 // sB2 dead
        float* sOut = smg;               // 64 x 65
        #pragma unroll
        for (int mi = 0; mi < 4; mi++) {
            int r = ty * 4 + mi;
            int row = row0 + r;
            *(float4*)(outS + (long)row * 64 + 4 * tx) =
                make_float4(ov[mi][0], ov[mi][1], ov[mi][2], ov[mi][3]);
            sOut[r * 65 + 4 * tx]     = ov[mi][0];
            sOut[r * 65 + 4 * tx + 1] = ov[mi][1];
            sOut[r * 65 + 4 * tx + 2] = ov[mi][2];
            sOut[r * 65 + 4 * tx + 3] = ov[mi][3];
        }
        __syncthreads();

        quantum_rows(sOut, sq, row0, 64, out0);
    } else {
        // =================== v branch: 128 rows of (3n+ii) ===================
        int row0 = (blockIdx.x - 128) * 128;
        float* sA  = smg;              // 128 x 132
        float* sB1 = smg + 16896;      // 128 x 36
        float* v1s = smg + S1OFF;      // 128 x 36

        for (int i4 = t; i4 < 128 * 32; i4 += 256) {
            int r = i4 >> 5, c4 = i4 & 31;
            *(float4*)(sA + r * 132 + c4 * 4) =
                *(const float4*)(g_agg_v + (long)(row0 + r) * 128 + c4 * 4);
        }
        for (int i4 = t; i4 < 128 * 8; i4 += 256) {
            int r = i4 >> 3, c4 = i4 & 7;
            *(float4*)(sB1 + r * 36 + c4 * 4) = *(const float4*)(Wd1 + r * 32 + c4 * 4);
        }
        __syncthreads();

        int tx = t & 7, ty = t >> 3;    // TX=8, TY=32, TM=4
        {
            ull acc[4][2];
            #pragma unroll
            for (int mi = 0; mi < 4; mi++) { acc[mi][0] = 0ull; acc[mi][1] = 0ull; }
            const float* aB = sA + ty * 4 * 132;
            const float* bB = sB1 + 4 * tx;
            #pragma unroll 4
            for (int k = 0; k < 128; k++) {
                ull b0 = lds64(bB + k * 36);
                ull b1 = lds64(bB + k * 36 + 2);
                #pragma unroll
                for (int mi = 0; mi < 4; mi++) {
                    ull ad = dup2(aB[mi * 132 + k]);
                    acc[mi][0] = fma2(b0, ad, acc[mi][0]);
                    acc[mi][1] = fma2(b1, ad, acc[mi][1]);
                }
            }
            #pragma unroll
            for (int mi = 0; mi < 4; mi++) {
                float v0, v1, v2, v3;
                unpack2(acc[mi][0], v0, v1);
                unpack2(acc[mi][1], v2, v3);
                *(float4*)(v1s + (ty * 4 + mi) * 36 + 4 * tx) =
                    make_float4(v0 * inv16, v1 * inv16, v2 * inv16, v3 * inv16);
            }
        }
        __syncthreads();

        float* sB2 = smg;              // 128 x 36
        for (int i4 = t; i4 < 128 * 8; i4 += 256) {
            int r = i4 >> 3, c4 = i4 & 7;
            *(float4*)(sB2 + r * 36 + c4 * 4) = *(const float4*)(Wt1 + r * 32 + c4 * 4);
        }
        float xr[4][4];
        #pragma unroll
        for (int mi = 0; mi < 4; mi++) {
            int rr = row0 + ty * 4 + mi;
            float4 xq = *(const float4*)(x_node + (rr / 3) * 4);
            xr[mi][0] = xq.x; xr[mi][1] = xq.y; xr[mi][2] = xq.z; xr[mi][3] = xq.w;
        }
        __syncthreads();

        {
            ull acc[4][2];
            #pragma unroll
            for (int mi = 0; mi < 4; mi++) { acc[mi][0] = 0ull; acc[mi][1] = 0ull; }
            const float* bB = sB2 + 4 * tx;
            const float* v1B = v1s + ty * 4 * 36;
            #pragma unroll 1
            for (int a = 0; a < 4; a++) {
                const float* bA = bB + a * 32 * 36;
                #pragma unroll 4
                for (int c = 0; c < 32; c++) {
                    ull b0 = lds64(bA + c * 36);
                    ull b1 = lds64(bA + c * 36 + 2);
                    #pragma unroll
                    for (int mi = 0; mi < 4; mi++) {
                        float sv = v1B[mi * 36 + c];
                        ull ad = dup2(xr[mi][a] * sv);
                        acc[mi][0] = fma2(b0, ad, acc[mi][0]);
                        acc[mi][1] = fma2(b1, ad, acc[mi][1]);
                    }
                }
            }
            #pragma unroll
            for (int mi = 0; mi < 4; mi++) {
                int row = row0 + ty * 4 + mi;
                float vv[4];
                unpack2(acc[mi][0], vv[0], vv[1]);
                unpack2(acc[mi][1], vv[2], vv[3]);
                int n = row / 3, ii = row - 3 * n;
                #pragma unroll
                for (int j = 0; j < 4; j++) {
                    int c = 4 * tx + j;
                    outV[(long)n * 96 + c * 3 + ii] =
                        vv[j] + g_skip_v[(long)n * 96 + c * 3 + ii];
                }
            }
        }
    }
}

// ---------------- launch ----------------
extern "C" void kernel_launch(void* const* d_in, const int* in_sizes, int n_in,
                              void* d_out, int out_size) {
    const float* s_in     = (const float*)d_in[0];
    const float* v_in     = (const float*)d_in[1];
    const float* x_node   = (const float*)d_in[2];
    const float* radial   = (const float*)d_in[3];
    const float* Y0       = (const float*)d_in[4];
    const float* Y1       = (const float*)d_in[5];
    const int*   species  = (const int*)d_in[6];
    const int*   senders  = (const int*)d_in[7];
    const int*   receivers= (const int*)d_in[8];
    const float* Wskip0   = (const float*)d_in[9];
    const float* Wskip1   = (const float*)d_in[10];
    const float* Wu0      = (const float*)d_in[11];
    const float* Wu1      = (const float*)d_in[12];
    const float* Wm1      = (const float*)d_in[13];
    const float* Wm2      = (const float*)d_in[14];
    const float* Wm3      = (const float*)d_in[15];
    const float* Wd0      = (const float*)d_in[16];
    const float* Wd1      = (const float*)d_in[17];
    const float* Wt0      = (const float*)d_in[18];
    const float* Wt1      = (const float*)d_in[19];
    const float* Wq       = (const float*)d_in[20];
    const float* wqml     = (const float*)d_in[21];
    const float* Wo       = (const float*)d_in[22];
    const float* bo       = (const float*)d_in[23];

    float* out0 = (float*)d_out;
    float* outS = out0 + Nn;
    float* outV = outS + Nn * C0;

    static bool attr_done = false;
    size_t smem_pre  = PRE_SMEM_FLOATS * sizeof(float);                    // ~120 KB
    size_t smem_edge = (23440 + EW * 2112) * sizeof(float);                // ~223.6 KB
    size_t smem_node = NODE_SMEM_FLOATS * sizeof(float);   // ~106.8 KB -> 2 blocks/SM
    if (!attr_done) {
        cudaFuncSetAttribute(node_pre_kernel, cudaFuncAttributeMaxDynamicSharedMemorySize, (int)smem_pre);
        cudaFuncSetAttribute(edge_kernel,     cudaFuncAttributeMaxDynamicSharedMemorySize, (int)smem_edge);
        cudaFuncSetAttribute(node_kernel,     cudaFuncAttributeMaxDynamicSharedMemorySize, (int)smem_node);
        attr_done = true;
    }

    node_pre_kernel<<<148, 512, smem_pre>>>(s_in, v_in, species, Wskip0, Wskip1, Wu0, Wu1);
    edge_kernel<<<148, 32 * EW, smem_edge>>>(radial, Y0, Y1, senders, receivers, Wm1, Wm2, Wm3);
    node_kernel<<<320, 256, smem_node>>>(Wd0, Wd1, Wt0, Wt1, x_node, Wq, wqml, Wo, bo,
                                         out0, outS, outV);
}